// round 4
// baseline (speedup 1.0000x reference)
#include <cuda_runtime.h>
#include <math.h>
#include <cstdint>

#define NB 8
#define CDIM 128
#define HH 192
#define WW 192
#define HWD (HH*WW)          // 36864
#define PTOT (NB*HWD)        // 294912
#define LROW 192
#define NROWS (NB*HH)        // 1536
#define BN_EPS 1e-5f

typedef unsigned long long ull;

// ---------------- f32x2 packed-math helpers ----------------
__device__ __forceinline__ ull pack2(float lo, float hi) {
    ull r;
    asm("mov.b64 %0, {%1, %2};" : "=l"(r) : "f"(lo), "f"(hi));
    return r;
}
__device__ __forceinline__ float2 unpack2(ull v) {
    float2 r;
    asm("mov.b64 {%0, %1}, %2;" : "=f"(r.x), "=f"(r.y) : "l"(v));
    return r;
}
__device__ __forceinline__ ull ffma2(ull a, ull b, ull c) {
    ull d;
    asm("fma.rn.f32x2 %0, %1, %2, %3;" : "=l"(d) : "l"(a), "l"(b), "l"(c));
    return d;
}
__device__ __forceinline__ ull fmul2(ull a, ull b) {
    ull d;
    asm("mul.rn.f32x2 %0, %1, %2;" : "=l"(d) : "l"(a), "l"(b));
    return d;
}

// ---------------- device scratch ----------------
__device__ float g_th [PTOT*CDIM];
__device__ float g_ph [PTOT*CDIM];
__device__ float g_g  [PTOT*CDIM];
__device__ float g_sch[PTOT*CDIM];
__device__ float g_scv[PTOT*CDIM];
__device__ float g_ah [PTOT*CDIM];
__device__ float g_av [PTOT*CDIM];

__device__ float g_Wall[CDIM*640];
__device__ float g_biasA[640];
__device__ float g_W3[CDIM*CDIM];
__device__ float g_b3[CDIM];
__device__ float g_W5[CDIM*CDIM];
__device__ float g_b5[CDIM];
__device__ float g_Wa[2*CDIM*CDIM];
__device__ float g_ba[CDIM];

// ---------------- BN folding prep ----------------
__global__ void prep_kernel(const float* __restrict__ W7, const float* __restrict__ m7,
                            const float* __restrict__ v7, const float* __restrict__ b7,
                            const float* __restrict__ Wa, const float* __restrict__ ma,
                            const float* __restrict__ va, const float* __restrict__ ba) {
    int t = blockIdx.x * blockDim.x + threadIdx.x;
    int stride = gridDim.x * blockDim.x;
    const int mats[5] = {0, 1, 2, 4, 6};
    for (int idx = t; idx < 128*640; idx += stride) {
        int k = idx / 640, j = idx % 640;
        int mi = j >> 7, d = j & 127;
        int m = mats[mi];
        float rs = rsqrtf(v7[m*128 + d] + BN_EPS);
        g_Wall[idx] = W7[(m*128 + k)*128 + d] * rs;
        if (k == 0) g_biasA[j] = b7[m*128 + d] - m7[m*128 + d]*rs;
    }
    for (int idx = t; idx < 128*128; idx += stride) {
        int k = idx >> 7, d = idx & 127;
        float rs3 = rsqrtf(v7[3*128 + d] + BN_EPS);
        float rs5 = rsqrtf(v7[5*128 + d] + BN_EPS);
        g_W3[idx] = W7[(3*128 + k)*128 + d] * rs3;
        g_W5[idx] = W7[(5*128 + k)*128 + d] * rs5;
        if (k == 0) {
            g_b3[d] = b7[3*128 + d] - m7[3*128 + d]*rs3;
            g_b5[d] = b7[5*128 + d] - m7[5*128 + d]*rs5;
        }
    }
    for (int idx = t; idx < 256*128; idx += stride) {
        int k = idx >> 7, d = idx & 127;
        float rs = rsqrtf(va[d] + BN_EPS);
        g_Wa[idx] = Wa[idx] * rs;
        if (k == 0) g_ba[d] = ba[d] - ma[d]*rs;
    }
}

// ---------------- 128x128x16 tiled GEMM, 8x4 lane mapping (LDS wavefront-optimized) ----------------
template<int MODE>
__global__ __launch_bounds__(256, 2) void gemm_kernel(const float* __restrict__ X) {
    __shared__ float Xs[16][132];
    __shared__ float Ws[16][128];
    const int tid = threadIdx.x;
    const int p0 = blockIdx.x * 128;
    // warp grid 2x4, lane grid 8x4: warp covers 64 rows x 32 cols
    const int wid = tid >> 5, lane = tid & 31;
    const int lr = lane & 7, lc = lane >> 3;
    const int wr = wid >> 2, wc = wid & 3;
    const int r0 = wr*64 + lr*8;
    const int c0 = wc*32 + lc*8;

    ull acc2[8][4];
#pragma unroll
    for (int i = 0; i < 8; i++)
#pragma unroll
        for (int q = 0; q < 4; q++) acc2[i][q] = 0ull;

    const int KTOT = (MODE == 2) ? 256 : 128;
    const float* Wp; int ldw; int wcol0;
    const float* xin = nullptr;
    if (MODE == 0) { Wp = g_Wall; ldw = 640; wcol0 = blockIdx.y * 128; }
    else if (MODE == 1) {
        Wp = blockIdx.y ? g_W5 : g_W3; ldw = 128; wcol0 = 0;
        xin = blockIdx.y ? g_av : g_ah;
    } else { Wp = g_Wa; ldw = 128; wcol0 = 0; }

    for (int k0 = 0; k0 < KTOT; k0 += 16) {
        if (MODE == 0) {
            int n = p0 / HWD, hw0 = p0 % HWD;
            const float* src = X + (size_t)n*CDIM*HWD + (size_t)k0*HWD + hw0;
#pragma unroll
            for (int i = 0; i < 8; i++) {
                int idx = tid + i*256;
                int k = idx >> 7, pl = idx & 127;
                Xs[k][pl] = src[(size_t)k*HWD + pl];
            }
        } else {
            const float* src;
            if (MODE == 1) src = xin + (size_t)p0*128 + k0;
            else           src = ((k0 < 128) ? g_th : g_ph) + (size_t)p0*128 + (k0 & 127);
#pragma unroll
            for (int i = 0; i < 2; i++) {
                int id = tid + i*256;
                int pl = id >> 2, kq = id & 3;
                float4 v = *(const float4*)(src + (size_t)pl*128 + kq*4);
                Xs[kq*4+0][pl] = v.x; Xs[kq*4+1][pl] = v.y;
                Xs[kq*4+2][pl] = v.z; Xs[kq*4+3][pl] = v.w;
            }
        }
#pragma unroll
        for (int i = 0; i < 8; i++) {
            int idx = tid + i*256;
            int k = idx >> 7, c = idx & 127;
            Ws[k][c] = Wp[(size_t)(k0 + k)*ldw + wcol0 + c];
        }
        __syncthreads();
#pragma unroll
        for (int kk = 0; kk < 16; kk++) {
            float a[8];
            float4 t0 = *(const float4*)&Xs[kk][r0];
            float4 t1 = *(const float4*)&Xs[kk][r0+4];
            a[0]=t0.x; a[1]=t0.y; a[2]=t0.z; a[3]=t0.w;
            a[4]=t1.x; a[5]=t1.y; a[6]=t1.z; a[7]=t1.w;
            longlong2 u0 = *(const longlong2*)&Ws[kk][c0];
            longlong2 u1 = *(const longlong2*)&Ws[kk][c0+4];
            ull b2[4] = {(ull)u0.x, (ull)u0.y, (ull)u1.x, (ull)u1.y};
#pragma unroll
            for (int i = 0; i < 8; i++) {
                ull ad = pack2(a[i], a[i]);
#pragma unroll
                for (int q = 0; q < 4; q++)
                    acc2[i][q] = ffma2(ad, b2[q], acc2[i][q]);
            }
        }
        __syncthreads();
    }

    float* outp; const float* biasp; const float* addp = nullptr; bool relu;
    if (MODE == 0) {
        int mat = blockIdx.y;
        outp = (mat==0) ? g_th : (mat==1) ? g_ph : (mat==2) ? g_g : (mat==3) ? g_sch : g_scv;
        biasp = g_biasA + mat*128;
        relu = (mat < 3);
    } else if (MODE == 1) {
        outp = blockIdx.y ? g_ph : g_th;
        biasp = blockIdx.y ? g_b5 : g_b3;
        addp  = blockIdx.y ? g_scv : g_sch;
        relu = true;
    } else { outp = g_g; biasp = g_ba; relu = true; }

    float bj[8];
#pragma unroll
    for (int j = 0; j < 8; j++) bj[j] = biasp[c0 + j];

#pragma unroll
    for (int i = 0; i < 8; i++) {
        size_t ro = (size_t)(p0 + r0 + i)*128 + c0;
        float r[8];
#pragma unroll
        for (int q = 0; q < 4; q++) {
            float2 u = unpack2(acc2[i][q]);
            r[q*2+0] = u.x + bj[q*2+0];
            r[q*2+1] = u.y + bj[q*2+1];
        }
        if (MODE == 1) {
            float4 a0 = *(const float4*)(addp + ro);
            float4 a1 = *(const float4*)(addp + ro + 4);
            r[0]+=a0.x; r[1]+=a0.y; r[2]+=a0.z; r[3]+=a0.w;
            r[4]+=a1.x; r[5]+=a1.y; r[6]+=a1.z; r[7]+=a1.w;
        }
        if (relu) {
#pragma unroll
            for (int j = 0; j < 8; j++) r[j] = fmaxf(r[j], 0.f);
        }
        *(float4*)(outp + ro)     = make_float4(r[0],r[1],r[2],r[3]);
        *(float4*)(outp + ro + 4) = make_float4(r[4],r[5],r[6],r[7]);
    }
}

// ---------------- axial attention (flash-style, fp32, K/V smem union, 8x4 lanes) ----------------
// smem: Qs[128][68] cmaj | KV (K cmaj [128][68] / V rowmaj [64][132]) | Ps[64][68] | red[128]
__global__ __launch_bounds__(256, 2) void attn_kernel() {
    extern __shared__ float sm[];
    float* Qs = sm;                  // 8704
    float* KV = Qs + 128*68;         // 8704 (union of K c-major and V row-major)
    float* Ps = KV + 128*68;         // 4352
    float* red_alpha = Ps + 64*68;   // 64
    float* red_l = red_alpha + 64;   // 64

    const int tid = threadIdx.x;
    const int q0 = blockIdx.x * 64;
    const int row = blockIdx.y;
    const int dir = blockIdx.z;

    size_t base; int stride;
    if (dir == 0) { base = (size_t)row * LROW * CDIM; stride = CDIM; }
    else {
        int n = row / WW, w = row % WW;
        base = (size_t)n*HH*WW*CDIM + (size_t)w*CDIM;
        stride = WW*CDIM;
    }
    const float* thp = g_th + base;
    const float* php = g_ph + base;
    const float* gp  = g_g  + base;
    float* outp = (dir == 0 ? g_ah : g_av) + base;

    // load Q [64][128] transposed into Qs[c][i]
#pragma unroll
    for (int t = 0; t < 8; t++) {
        int id = tid + t*256;
        int i = id >> 5, cq = (id & 31)*4;
        float4 v = *(const float4*)(thp + (size_t)(q0 + i)*stride + cq);
        Qs[(cq+0)*68 + i] = v.x; Qs[(cq+1)*68 + i] = v.y;
        Qs[(cq+2)*68 + i] = v.z; Qs[(cq+3)*68 + i] = v.w;
    }

    // 8x4 lane grid; warps 2x4 over (i-blocks 16) x (j/c-blocks 16)
    const int wid = tid >> 5, lane = tid & 31;
    const int lr = lane & 7, lc = lane >> 3;
    const int ti = (wid & 1)*8 + lr;     // 0..15
    const int tj = (wid >> 1)*4 + lc;    // 0..15
    const int i0 = ti*4, j0 = tj*4, cc0 = tj*8;
    const int grow = tid >> 2, slane = tid & 3;

    ull o2[4][4];
#pragma unroll
    for (int i = 0; i < 4; i++)
#pragma unroll
        for (int q = 0; q < 4; q++) o2[i][q] = 0ull;
    float m_run = -1e30f, l_run = 0.f;
    const float scale = 0.08838834764831845f;  // 1/sqrt(128)

    for (int kb = 0; kb < LROW; kb += 64) {
        __syncthreads();   // prev chunk's PV done reading KV(V); Ps free
        // load K chunk transposed into KV[c][j]
#pragma unroll
        for (int t = 0; t < 8; t++) {
            int id = tid + t*256;
            int j = id >> 5, cq = (id & 31)*4;
            float4 v = *(const float4*)(php + (size_t)(kb + j)*stride + cq);
            KV[(cq+0)*68 + j] = v.x; KV[(cq+1)*68 + j] = v.y;
            KV[(cq+2)*68 + j] = v.z; KV[(cq+3)*68 + j] = v.w;
        }
        __syncthreads();

        // S[64][64] = Q K^T * scale
        ull s2[4][2];
#pragma unroll
        for (int i = 0; i < 4; i++) { s2[i][0] = 0ull; s2[i][1] = 0ull; }
#pragma unroll 8
        for (int c = 0; c < CDIM; c++) {
            float4 q4 = *(const float4*)&Qs[c*68 + i0];
            float aq[4] = {q4.x, q4.y, q4.z, q4.w};
            longlong2 kk2 = *(const longlong2*)&KV[c*68 + j0];
            ull k2[2] = {(ull)kk2.x, (ull)kk2.y};
#pragma unroll
            for (int i = 0; i < 4; i++) {
                ull ad = pack2(aq[i], aq[i]);
                s2[i][0] = ffma2(ad, k2[0], s2[i][0]);
                s2[i][1] = ffma2(ad, k2[1], s2[i][1]);
            }
        }
#pragma unroll
        for (int i = 0; i < 4; i++) {
            float2 p0f = unpack2(s2[i][0]);
            float2 p1f = unpack2(s2[i][1]);
            *(float4*)&Ps[(i0 + i)*68 + j0] =
                make_float4(p0f.x*scale, p0f.y*scale, p1f.x*scale, p1f.y*scale);
        }
        __syncthreads();   // Ps visible; K reads done -> KV reusable for V

        // load V chunk row-major into KV[j][132]  (overlapped with softmax below)
#pragma unroll
        for (int t = 0; t < 8; t++) {
            int id = tid + t*256;
            int j = id >> 5, cq = (id & 31)*4;
            *(float4*)&KV[j*132 + cq] = *(const float4*)(gp + (size_t)(kb + j)*stride + cq);
        }

        // online softmax per row (4 threads/row on Ps)
        float mx = -1e30f;
#pragma unroll
        for (int jj = 0; jj < 16; jj++)
            mx = fmaxf(mx, Ps[grow*68 + jj*4 + slane]);
        mx = fmaxf(mx, __shfl_xor_sync(0xffffffffu, mx, 1));
        mx = fmaxf(mx, __shfl_xor_sync(0xffffffffu, mx, 2));
        float m_new = fmaxf(m_run, mx);
        float alpha = __expf(m_run - m_new);
        float ssum = 0.f;
#pragma unroll
        for (int jj = 0; jj < 16; jj++) {
            int idx = grow*68 + jj*4 + slane;
            float e = __expf(Ps[idx] - m_new);
            Ps[idx] = e;
            ssum += e;
        }
        ssum += __shfl_xor_sync(0xffffffffu, ssum, 1);
        ssum += __shfl_xor_sync(0xffffffffu, ssum, 2);
        l_run = l_run * alpha + ssum;
        m_run = m_new;
        if (slane == 0) red_alpha[grow] = alpha;
        __syncthreads();   // V + exp(Ps) + alpha visible

        // O = O*alpha + P V
#pragma unroll
        for (int i = 0; i < 4; i++) {
            float al = red_alpha[i0 + i];
            ull ap = pack2(al, al);
#pragma unroll
            for (int q = 0; q < 4; q++) o2[i][q] = fmul2(o2[i][q], ap);
        }
#pragma unroll 4
        for (int j = 0; j < 64; j++) {
            longlong2 v0 = *(const longlong2*)&KV[j*132 + cc0];
            longlong2 v1 = *(const longlong2*)&KV[j*132 + cc0 + 4];
            ull vv[4] = {(ull)v0.x, (ull)v0.y, (ull)v1.x, (ull)v1.y};
            float pp[4];
#pragma unroll
            for (int i = 0; i < 4; i++) pp[i] = Ps[(i0 + i)*68 + j];
#pragma unroll
            for (int i = 0; i < 4; i++) {
                ull pd = pack2(pp[i], pp[i]);
#pragma unroll
                for (int q = 0; q < 4; q++)
                    o2[i][q] = ffma2(pd, vv[q], o2[i][q]);
            }
        }
    }

    if (slane == 0) red_l[grow] = l_run;
    __syncthreads();
#pragma unroll
    for (int i = 0; i < 4; i++) {
        float inv = 1.f / red_l[i0 + i];
        ull ip = pack2(inv, inv);
        float2 r0f = unpack2(fmul2(o2[i][0], ip));
        float2 r1f = unpack2(fmul2(o2[i][1], ip));
        float2 r2f = unpack2(fmul2(o2[i][2], ip));
        float2 r3f = unpack2(fmul2(o2[i][3], ip));
        float* dst = outp + (size_t)(q0 + i0 + i)*stride + cc0;
        *(float4*)dst       = make_float4(r0f.x, r0f.y, r1f.x, r1f.y);
        *(float4*)(dst + 4) = make_float4(r2f.x, r2f.y, r3f.x, r3f.y);
    }
}

// ---------------- NHWC -> NCHW output transpose ----------------
__global__ void transpose_out(float* __restrict__ out) {
    __shared__ float tile[32][33];
    int n = blockIdx.z;
    int hw0 = blockIdx.x * 32;
    int c0 = blockIdx.y * 32;
    int tx = threadIdx.x, ty = threadIdx.y;
    const float* src = g_g + (size_t)n*HWD*CDIM;
#pragma unroll
    for (int i = 0; i < 32; i += 8)
        tile[ty + i][tx] = src[(size_t)(hw0 + ty + i)*CDIM + c0 + tx];
    __syncthreads();
    float* dst = out + (size_t)n*CDIM*HWD;
#pragma unroll
    for (int i = 0; i < 32; i += 8)
        dst[(size_t)(c0 + ty + i)*HWD + hw0 + tx] = tile[tx][ty + i];
}

// ---------------- launch ----------------
extern "C" void kernel_launch(void* const* d_in, const int* in_sizes, int n_in,
                              void* d_out, int out_size) {
    const float* f  = (const float*)d_in[0];
    const float* W7 = (const float*)d_in[1];
    const float* m7 = (const float*)d_in[2];
    const float* v7 = (const float*)d_in[3];
    const float* b7 = (const float*)d_in[4];
    const float* Wa = (const float*)d_in[5];
    const float* ma = (const float*)d_in[6];
    const float* va = (const float*)d_in[7];
    const float* ba = (const float*)d_in[8];
    float* out = (float*)d_out;

    prep_kernel<<<64, 256>>>(W7, m7, v7, b7, Wa, ma, va, ba);

    gemm_kernel<0><<<dim3(PTOT/128, 5), 256>>>(f);

    // attention: Qs + KV(union) + Ps + red = 8704+8704+4352+128 floats
    int smem_bytes = (8704 + 8704 + 4352 + 128) * 4;
    cudaFuncSetAttribute(attn_kernel, cudaFuncAttributeMaxDynamicSharedMemorySize, smem_bytes);
    attn_kernel<<<dim3(LROW/64, NROWS, 2), 256, smem_bytes>>>();

    gemm_kernel<1><<<dim3(PTOT/128, 2), 256>>>(nullptr);
    gemm_kernel<2><<<dim3(PTOT/128, 1), 256>>>(nullptr);

    transpose_out<<<dim3(HWD/32, CDIM/32, NB), dim3(32, 8)>>>(out);
}

// round 5
// speedup vs baseline: 1.0571x; 1.0571x over previous
#include <cuda_runtime.h>
#include <math.h>
#include <cstdint>

#define NB 8
#define CDIM 128
#define HH 192
#define WW 192
#define HWD (HH*WW)          // 36864
#define PTOT (NB*HWD)        // 294912
#define LROW 192
#define NROWS (NB*HH)        // 1536
#define BN_EPS 1e-5f

typedef unsigned long long ull;

// ---------------- f32x2 packed-math helpers ----------------
__device__ __forceinline__ ull pack2(float lo, float hi) {
    ull r;
    asm("mov.b64 %0, {%1, %2};" : "=l"(r) : "f"(lo), "f"(hi));
    return r;
}
__device__ __forceinline__ float2 unpack2(ull v) {
    float2 r;
    asm("mov.b64 {%0, %1}, %2;" : "=f"(r.x), "=f"(r.y) : "l"(v));
    return r;
}
__device__ __forceinline__ ull ffma2(ull a, ull b, ull c) {
    ull d;
    asm("fma.rn.f32x2 %0, %1, %2, %3;" : "=l"(d) : "l"(a), "l"(b), "l"(c));
    return d;
}
__device__ __forceinline__ ull fmul2(ull a, ull b) {
    ull d;
    asm("mul.rn.f32x2 %0, %1, %2;" : "=l"(d) : "l"(a), "l"(b));
    return d;
}

// ---------------- cp.async helpers (sm_80+, family-portable) ----------------
__device__ __forceinline__ void cpa16(uint32_t s, const float* g) {
    asm volatile("cp.async.ca.shared.global [%0], [%1], 16;" :: "r"(s), "l"(g));
}
#define CP_COMMIT() asm volatile("cp.async.commit_group;" ::: "memory")
#define CP_WAIT0()  asm volatile("cp.async.wait_group 0;" ::: "memory")

// ---------------- device scratch ----------------
__device__ float g_th [PTOT*CDIM];
__device__ float g_ph [PTOT*CDIM];
__device__ float g_g  [PTOT*CDIM];
__device__ float g_sch[PTOT*CDIM];
__device__ float g_scv[PTOT*CDIM];
__device__ float g_ah [PTOT*CDIM];
__device__ float g_av [PTOT*CDIM];

__device__ float g_Wall[CDIM*640];
__device__ float g_biasA[640];
__device__ float g_W3[CDIM*CDIM];
__device__ float g_b3[CDIM];
__device__ float g_W5[CDIM*CDIM];
__device__ float g_b5[CDIM];
__device__ float g_Wa[2*CDIM*CDIM];
__device__ float g_ba[CDIM];

// ---------------- BN folding prep ----------------
__global__ void prep_kernel(const float* __restrict__ W7, const float* __restrict__ m7,
                            const float* __restrict__ v7, const float* __restrict__ b7,
                            const float* __restrict__ Wa, const float* __restrict__ ma,
                            const float* __restrict__ va, const float* __restrict__ ba) {
    int t = blockIdx.x * blockDim.x + threadIdx.x;
    int stride = gridDim.x * blockDim.x;
    const int mats[5] = {0, 1, 2, 4, 6};
    for (int idx = t; idx < 128*640; idx += stride) {
        int k = idx / 640, j = idx % 640;
        int mi = j >> 7, d = j & 127;
        int m = mats[mi];
        float rs = rsqrtf(v7[m*128 + d] + BN_EPS);
        g_Wall[idx] = W7[(m*128 + k)*128 + d] * rs;
        if (k == 0) g_biasA[j] = b7[m*128 + d] - m7[m*128 + d]*rs;
    }
    for (int idx = t; idx < 128*128; idx += stride) {
        int k = idx >> 7, d = idx & 127;
        float rs3 = rsqrtf(v7[3*128 + d] + BN_EPS);
        float rs5 = rsqrtf(v7[5*128 + d] + BN_EPS);
        g_W3[idx] = W7[(3*128 + k)*128 + d] * rs3;
        g_W5[idx] = W7[(5*128 + k)*128 + d] * rs5;
        if (k == 0) {
            g_b3[d] = b7[3*128 + d] - m7[3*128 + d]*rs3;
            g_b5[d] = b7[5*128 + d] - m7[5*128 + d]*rs5;
        }
    }
    for (int idx = t; idx < 256*128; idx += stride) {
        int k = idx >> 7, d = idx & 127;
        float rs = rsqrtf(va[d] + BN_EPS);
        g_Wa[idx] = Wa[idx] * rs;
        if (k == 0) g_ba[d] = ba[d] - ma[d]*rs;
    }
}

// ---------------- 128x128x16 tiled GEMM, cp.async double-buffered ----------------
// Thread map (reverted to R3): ty=tid>>4 (0..15) -> r0=ty*8, tx=tid&15 -> c0=tx*8.
// MODE 0: X NCHW -> SX k-major [16][132]. MODE 1/2: X NHWC rows -> SX pixel-major [128][20].
template<int MODE>
__global__ __launch_bounds__(256, 2) void gemm_kernel(const float* __restrict__ X) {
    __shared__ __align__(16) float SX[2][2560];      // k-major 16*132=2112 | pix-major 128*20=2560
    __shared__ __align__(16) float SW[2][16][128];
    const int tid = threadIdx.x;
    const int p0 = blockIdx.x * 128;
    const int ty = tid >> 4, tx = tid & 15;
    const int r0 = ty * 8, c0 = tx * 8;

    ull acc2[8][4];
#pragma unroll
    for (int i = 0; i < 8; i++)
#pragma unroll
        for (int q = 0; q < 4; q++) acc2[i][q] = 0ull;

    const int KT = (MODE == 2) ? 16 : 8;   // number of 16-wide k tiles
    const float* Wp; int ldw; int wcol0;
    const float* xin = nullptr;
    if (MODE == 0) { Wp = g_Wall; ldw = 640; wcol0 = blockIdx.y * 128; }
    else if (MODE == 1) {
        Wp = blockIdx.y ? g_W5 : g_W3; ldw = 128; wcol0 = 0;
        xin = blockIdx.y ? g_av : g_ah;
    } else { Wp = g_Wa; ldw = 128; wcol0 = 0; }

    const int n_img = p0 / HWD, hw0 = p0 % HWD;
    uint32_t sx_base = (uint32_t)__cvta_generic_to_shared(&SX[0][0]);
    uint32_t sw_base = (uint32_t)__cvta_generic_to_shared(&SW[0][0][0]);

    // tile loader: issues 4 cp.async per thread (X: 2, W: 2)
    auto load_tile = [&](int t, int buf) {
        int k0 = t * 16;
        uint32_t sxb = sx_base + buf * 2560 * 4;
        uint32_t swb = sw_base + buf * 16 * 128 * 4;
        if (MODE == 0) {
            const float* src = X + (size_t)n_img*CDIM*HWD + (size_t)k0*HWD + hw0;
#pragma unroll
            for (int i = 0; i < 2; i++) {
                int id = tid + i*256;              // 512 16B chunks
                int k = id >> 5, quad = id & 31;
                cpa16(sxb + (uint32_t)(k*132 + quad*4)*4, src + (size_t)k*HWD + quad*4);
            }
        } else {
            const float* src;
            if (MODE == 1) src = xin + (size_t)p0*128 + k0;
            else           src = ((k0 < 128) ? g_th : g_ph) + (size_t)p0*128 + (k0 & 127);
#pragma unroll
            for (int i = 0; i < 2; i++) {
                int id = tid + i*256;              // 512 16B chunks
                int p = id >> 2, q = id & 3;
                cpa16(sxb + (uint32_t)(p*20 + q*4)*4, src + (size_t)p*128 + q*4);
            }
        }
        const float* wsrc = Wp + (size_t)k0*ldw + wcol0;
#pragma unroll
        for (int i = 0; i < 2; i++) {
            int id = tid + i*256;
            int k = id >> 5, quad = id & 31;
            cpa16(swb + (uint32_t)(k*128 + quad*4)*4, wsrc + (size_t)k*ldw + quad*4);
        }
        CP_COMMIT();
    };

    load_tile(0, 0);
    int buf = 0;
    for (int t = 0; t < KT; t++) {
        CP_WAIT0();
        __syncthreads();
        if (t + 1 < KT) load_tile(t + 1, buf ^ 1);

        const float* xs = &SX[0][0] + buf * 2560;
        const float (*ws)[128] = SW[buf];
        if (MODE == 0) {
            // k-major: per kk, A broadcast float4s, B contiguous pairs
#pragma unroll
            for (int kk = 0; kk < 16; kk++) {
                float a[8];
                float4 t0 = *(const float4*)&xs[kk*132 + r0];
                float4 t1 = *(const float4*)&xs[kk*132 + r0 + 4];
                a[0]=t0.x; a[1]=t0.y; a[2]=t0.z; a[3]=t0.w;
                a[4]=t1.x; a[5]=t1.y; a[6]=t1.z; a[7]=t1.w;
                longlong2 u0 = *(const longlong2*)&ws[kk][c0];
                longlong2 u1 = *(const longlong2*)&ws[kk][c0+4];
                ull b2[4] = {(ull)u0.x, (ull)u0.y, (ull)u1.x, (ull)u1.y};
#pragma unroll
                for (int i = 0; i < 8; i++) {
                    ull ad = pack2(a[i], a[i]);
#pragma unroll
                    for (int q = 0; q < 4; q++)
                        acc2[i][q] = ffma2(ad, b2[q], acc2[i][q]);
                }
            }
        } else {
            // pixel-major: process 4 kk per A-load round (float4 over k)
#pragma unroll
            for (int k4 = 0; k4 < 4; k4++) {
                float4 a4[8];
#pragma unroll
                for (int i = 0; i < 8; i++)
                    a4[i] = *(const float4*)&xs[(r0 + i)*20 + k4*4];
#pragma unroll
                for (int st = 0; st < 4; st++) {
                    int kk = k4*4 + st;
                    longlong2 u0 = *(const longlong2*)&ws[kk][c0];
                    longlong2 u1 = *(const longlong2*)&ws[kk][c0+4];
                    ull b2[4] = {(ull)u0.x, (ull)u0.y, (ull)u1.x, (ull)u1.y};
#pragma unroll
                    for (int i = 0; i < 8; i++) {
                        float av = (st == 0) ? a4[i].x : (st == 1) ? a4[i].y
                                 : (st == 2) ? a4[i].z : a4[i].w;
                        ull ad = pack2(av, av);
#pragma unroll
                        for (int q = 0; q < 4; q++)
                            acc2[i][q] = ffma2(ad, b2[q], acc2[i][q]);
                    }
                }
            }
        }
        __syncthreads();
        buf ^= 1;
    }

    float* outp; const float* biasp; const float* addp = nullptr; bool relu;
    if (MODE == 0) {
        int mat = blockIdx.y;
        outp = (mat==0) ? g_th : (mat==1) ? g_ph : (mat==2) ? g_g : (mat==3) ? g_sch : g_scv;
        biasp = g_biasA + mat*128;
        relu = (mat < 3);
    } else if (MODE == 1) {
        outp = blockIdx.y ? g_ph : g_th;
        biasp = blockIdx.y ? g_b5 : g_b3;
        addp  = blockIdx.y ? g_scv : g_sch;
        relu = true;
    } else { outp = g_g; biasp = g_ba; relu = true; }

    float bj[8];
#pragma unroll
    for (int j = 0; j < 8; j++) bj[j] = biasp[c0 + j];

#pragma unroll
    for (int i = 0; i < 8; i++) {
        size_t ro = (size_t)(p0 + r0 + i)*128 + c0;
        float r[8];
#pragma unroll
        for (int q = 0; q < 4; q++) {
            float2 u = unpack2(acc2[i][q]);
            r[q*2+0] = u.x + bj[q*2+0];
            r[q*2+1] = u.y + bj[q*2+1];
        }
        if (MODE == 1) {
            float4 a0 = *(const float4*)(addp + ro);
            float4 a1 = *(const float4*)(addp + ro + 4);
            r[0]+=a0.x; r[1]+=a0.y; r[2]+=a0.z; r[3]+=a0.w;
            r[4]+=a1.x; r[5]+=a1.y; r[6]+=a1.z; r[7]+=a1.w;
        }
        if (relu) {
#pragma unroll
            for (int j = 0; j < 8; j++) r[j] = fmaxf(r[j], 0.f);
        }
        *(float4*)(outp + ro)     = make_float4(r[0],r[1],r[2],r[3]);
        *(float4*)(outp + ro + 4) = make_float4(r[4],r[5],r[6],r[7]);
    }
}

// ---------------- axial attention (flash-style, fp32, K/V smem union, 2 CTAs/SM) ----------------
__global__ __launch_bounds__(256, 2) void attn_kernel() {
    extern __shared__ float sm[];
    float* Qs = sm;                  // 8704
    float* KV = Qs + 128*68;         // 8704 (union: K c-major / V row-major)
    float* Ps = KV + 128*68;         // 4352
    float* red_alpha = Ps + 64*68;   // 64
    float* red_l = red_alpha + 64;   // 64

    const int tid = threadIdx.x;
    const int q0 = blockIdx.x * 64;
    const int row = blockIdx.y;
    const int dir = blockIdx.z;

    size_t base; int stride;
    if (dir == 0) { base = (size_t)row * LROW * CDIM; stride = CDIM; }
    else {
        int n = row / WW, w = row % WW;
        base = (size_t)n*HH*WW*CDIM + (size_t)w*CDIM;
        stride = WW*CDIM;
    }
    const float* thp = g_th + base;
    const float* php = g_ph + base;
    const float* gp  = g_g  + base;
    float* outp = (dir == 0 ? g_ah : g_av) + base;

#pragma unroll
    for (int t = 0; t < 8; t++) {
        int id = tid + t*256;
        int i = id >> 5, cq = (id & 31)*4;
        float4 v = *(const float4*)(thp + (size_t)(q0 + i)*stride + cq);
        Qs[(cq+0)*68 + i] = v.x; Qs[(cq+1)*68 + i] = v.y;
        Qs[(cq+2)*68 + i] = v.z; Qs[(cq+3)*68 + i] = v.w;
    }

    const int wid = tid >> 5, lane = tid & 31;
    const int lr = lane & 7, lc = lane >> 3;
    const int ti = (wid & 1)*8 + lr;
    const int tj = (wid >> 1)*4 + lc;
    const int i0 = ti*4, j0 = tj*4, cc0 = tj*8;
    const int grow = tid >> 2, slane = tid & 3;

    ull o2[4][4];
#pragma unroll
    for (int i = 0; i < 4; i++)
#pragma unroll
        for (int q = 0; q < 4; q++) o2[i][q] = 0ull;
    float m_run = -1e30f, l_run = 0.f;
    const float scale = 0.08838834764831845f;

    for (int kb = 0; kb < LROW; kb += 64) {
        __syncthreads();
#pragma unroll
        for (int t = 0; t < 8; t++) {
            int id = tid + t*256;
            int j = id >> 5, cq = (id & 31)*4;
            float4 v = *(const float4*)(php + (size_t)(kb + j)*stride + cq);
            KV[(cq+0)*68 + j] = v.x; KV[(cq+1)*68 + j] = v.y;
            KV[(cq+2)*68 + j] = v.z; KV[(cq+3)*68 + j] = v.w;
        }
        __syncthreads();

        ull s2[4][2];
#pragma unroll
        for (int i = 0; i < 4; i++) { s2[i][0] = 0ull; s2[i][1] = 0ull; }
#pragma unroll 8
        for (int c = 0; c < CDIM; c++) {
            float4 q4 = *(const float4*)&Qs[c*68 + i0];
            float aq[4] = {q4.x, q4.y, q4.z, q4.w};
            longlong2 kk2 = *(const longlong2*)&KV[c*68 + j0];
            ull k2[2] = {(ull)kk2.x, (ull)kk2.y};
#pragma unroll
            for (int i = 0; i < 4; i++) {
                ull ad = pack2(aq[i], aq[i]);
                s2[i][0] = ffma2(ad, k2[0], s2[i][0]);
                s2[i][1] = ffma2(ad, k2[1], s2[i][1]);
            }
        }
#pragma unroll
        for (int i = 0; i < 4; i++) {
            float2 p0f = unpack2(s2[i][0]);
            float2 p1f = unpack2(s2[i][1]);
            *(float4*)&Ps[(i0 + i)*68 + j0] =
                make_float4(p0f.x*scale, p0f.y*scale, p1f.x*scale, p1f.y*scale);
        }
        __syncthreads();

#pragma unroll
        for (int t = 0; t < 8; t++) {
            int id = tid + t*256;
            int j = id >> 5, cq = (id & 31)*4;
            *(float4*)&KV[j*132 + cq] = *(const float4*)(gp + (size_t)(kb + j)*stride + cq);
        }

        float mx = -1e30f;
#pragma unroll
        for (int jj = 0; jj < 16; jj++)
            mx = fmaxf(mx, Ps[grow*68 + jj*4 + slane]);
        mx = fmaxf(mx, __shfl_xor_sync(0xffffffffu, mx, 1));
        mx = fmaxf(mx, __shfl_xor_sync(0xffffffffu, mx, 2));
        float m_new = fmaxf(m_run, mx);
        float alpha = __expf(m_run - m_new);
        float ssum = 0.f;
#pragma unroll
        for (int jj = 0; jj < 16; jj++) {
            int idx = grow*68 + jj*4 + slane;
            float e = __expf(Ps[idx] - m_new);
            Ps[idx] = e;
            ssum += e;
        }
        ssum += __shfl_xor_sync(0xffffffffu, ssum, 1);
        ssum += __shfl_xor_sync(0xffffffffu, ssum, 2);
        l_run = l_run * alpha + ssum;
        m_run = m_new;
        if (slane == 0) red_alpha[grow] = alpha;
        __syncthreads();

#pragma unroll
        for (int i = 0; i < 4; i++) {
            float al = red_alpha[i0 + i];
            ull ap = pack2(al, al);
#pragma unroll
            for (int q = 0; q < 4; q++) o2[i][q] = fmul2(o2[i][q], ap);
        }
#pragma unroll 4
        for (int j = 0; j < 64; j++) {
            longlong2 v0 = *(const longlong2*)&KV[j*132 + cc0];
            longlong2 v1 = *(const longlong2*)&KV[j*132 + cc0 + 4];
            ull vv[4] = {(ull)v0.x, (ull)v0.y, (ull)v1.x, (ull)v1.y};
            float pp[4];
#pragma unroll
            for (int i = 0; i < 4; i++) pp[i] = Ps[(i0 + i)*68 + j];
#pragma unroll
            for (int i = 0; i < 4; i++) {
                ull pd = pack2(pp[i], pp[i]);
#pragma unroll
                for (int q = 0; q < 4; q++)
                    o2[i][q] = ffma2(pd, vv[q], o2[i][q]);
            }
        }
    }

    if (slane == 0) red_l[grow] = l_run;
    __syncthreads();
#pragma unroll
    for (int i = 0; i < 4; i++) {
        float inv = 1.f / red_l[i0 + i];
        ull ip = pack2(inv, inv);
        float2 r0f = unpack2(fmul2(o2[i][0], ip));
        float2 r1f = unpack2(fmul2(o2[i][1], ip));
        float2 r2f = unpack2(fmul2(o2[i][2], ip));
        float2 r3f = unpack2(fmul2(o2[i][3], ip));
        float* dst = outp + (size_t)(q0 + i0 + i)*stride + cc0;
        *(float4*)dst       = make_float4(r0f.x, r0f.y, r1f.x, r1f.y);
        *(float4*)(dst + 4) = make_float4(r2f.x, r2f.y, r3f.x, r3f.y);
    }
}

// ---------------- NHWC -> NCHW output transpose ----------------
__global__ void transpose_out(float* __restrict__ out) {
    __shared__ float tile[32][33];
    int n = blockIdx.z;
    int hw0 = blockIdx.x * 32;
    int c0 = blockIdx.y * 32;
    int tx = threadIdx.x, ty = threadIdx.y;
    const float* src = g_g + (size_t)n*HWD*CDIM;
#pragma unroll
    for (int i = 0; i < 32; i += 8)
        tile[ty + i][tx] = src[(size_t)(hw0 + ty + i)*CDIM + c0 + tx];
    __syncthreads();
    float* dst = out + (size_t)n*CDIM*HWD;
#pragma unroll
    for (int i = 0; i < 32; i += 8)
        dst[(size_t)(c0 + ty + i)*HWD + hw0 + tx] = tile[tx][ty + i];
}

// ---------------- launch ----------------
extern "C" void kernel_launch(void* const* d_in, const int* in_sizes, int n_in,
                              void* d_out, int out_size) {
    const float* f  = (const float*)d_in[0];
    const float* W7 = (const float*)d_in[1];
    const float* m7 = (const float*)d_in[2];
    const float* v7 = (const float*)d_in[3];
    const float* b7 = (const float*)d_in[4];
    const float* Wa = (const float*)d_in[5];
    const float* ma = (const float*)d_in[6];
    const float* va = (const float*)d_in[7];
    const float* ba = (const float*)d_in[8];
    float* out = (float*)d_out;

    prep_kernel<<<64, 256>>>(W7, m7, v7, b7, Wa, ma, va, ba);

    gemm_kernel<0><<<dim3(PTOT/128, 5), 256>>>(f);

    int smem_bytes = (8704 + 8704 + 4352 + 128) * 4;
    cudaFuncSetAttribute(attn_kernel, cudaFuncAttributeMaxDynamicSharedMemorySize, smem_bytes);
    attn_kernel<<<dim3(LROW/64, NROWS, 2), 256, smem_bytes>>>();

    gemm_kernel<1><<<dim3(PTOT/128, 2), 256>>>(nullptr);
    gemm_kernel<2><<<dim3(PTOT/128, 1), 256>>>(nullptr);

    transpose_out<<<dim3(HWD/32, CDIM/32, NB), dim3(32, 8)>>>(out);
}

// round 6
// speedup vs baseline: 1.3728x; 1.2986x over previous
#include <cuda_runtime.h>
#include <math.h>
#include <cstdint>

#define NB 8
#define CDIM 128
#define HH 192
#define WW 192
#define HWD (HH*WW)          // 36864
#define PTOT (NB*HWD)        // 294912
#define LROW 192
#define NROWS (NB*HH)        // 1536
#define BN_EPS 1e-5f

typedef unsigned long long ull;

// ---------------- f32x2 packed-math helpers (attention) ----------------
__device__ __forceinline__ ull pack2(float lo, float hi) {
    ull r;
    asm("mov.b64 %0, {%1, %2};" : "=l"(r) : "f"(lo), "f"(hi));
    return r;
}
__device__ __forceinline__ float2 unpack2(ull v) {
    float2 r;
    asm("mov.b64 {%0, %1}, %2;" : "=f"(r.x), "=f"(r.y) : "l"(v));
    return r;
}
__device__ __forceinline__ ull ffma2(ull a, ull b, ull c) {
    ull d;
    asm("fma.rn.f32x2 %0, %1, %2, %3;" : "=l"(d) : "l"(a), "l"(b), "l"(c));
    return d;
}
__device__ __forceinline__ ull fmul2(ull a, ull b) {
    ull d;
    asm("mul.rn.f32x2 %0, %1, %2;" : "=l"(d) : "l"(a), "l"(b));
    return d;
}

// ---------------- cp.async / ldmatrix / mma helpers (family-portable) ----------------
__device__ __forceinline__ void cpa16(uint32_t s, const float* g) {
    asm volatile("cp.async.ca.shared.global [%0], [%1], 16;" :: "r"(s), "l"(g));
}
#define CP_COMMIT() asm volatile("cp.async.commit_group;" ::: "memory")
#define CP_WAIT0()  asm volatile("cp.async.wait_group 0;" ::: "memory")

__device__ __forceinline__ void ldm4(uint32_t* r, uint32_t addr) {
    asm volatile("ldmatrix.sync.aligned.m8n8.x4.shared.b16 {%0,%1,%2,%3}, [%4];"
                 : "=r"(r[0]), "=r"(r[1]), "=r"(r[2]), "=r"(r[3]) : "r"(addr));
}
__device__ __forceinline__ uint32_t f2tf(uint32_t x) {
    uint32_t y;
    asm("cvt.rna.tf32.f32 %0, %1;" : "=r"(y) : "r"(x));
    return y;
}
__device__ __forceinline__ void mma_tf32(float* d, const uint32_t* a, const uint32_t* b) {
    asm volatile(
        "mma.sync.aligned.m16n8k8.row.col.f32.tf32.tf32.f32 "
        "{%0,%1,%2,%3}, {%4,%5,%6,%7}, {%8,%9}, {%0,%1,%2,%3};"
        : "+f"(d[0]), "+f"(d[1]), "+f"(d[2]), "+f"(d[3])
        : "r"(a[0]), "r"(a[1]), "r"(a[2]), "r"(a[3]), "r"(b[0]), "r"(b[1]));
}

// ---------------- device scratch ----------------
__device__ float g_th [PTOT*CDIM];   // theta, later u = f_h
__device__ float g_ph [PTOT*CDIM];   // phi,   later v = f_v
__device__ float g_g  [PTOT*CDIM];   // g,     later final NHWC tmp
__device__ float g_sch[PTOT*CDIM];
__device__ float g_scv[PTOT*CDIM];
__device__ float g_ah [PTOT*CDIM];   // f_common NHWC before attention; attn-h out after
__device__ float g_av [PTOT*CDIM];

__device__ float g_WtA[5*CDIM*CDIM]; // [mat][d][k] folded, transposed, tf32-rounded
__device__ float g_biasA[5*CDIM];
__device__ float g_Wt3[CDIM*CDIM];   // [d][k]
__device__ float g_b3[CDIM];
__device__ float g_Wt5[CDIM*CDIM];
__device__ float g_b5[CDIM];
__device__ float g_WtF[CDIM*2*CDIM]; // [d][kk] kk<256
__device__ float g_ba[CDIM];

// ---------------- BN folding prep (transposed + tf32-rounded weights) ----------------
__global__ void prep_kernel(const float* __restrict__ W7, const float* __restrict__ m7,
                            const float* __restrict__ v7, const float* __restrict__ b7,
                            const float* __restrict__ Wa, const float* __restrict__ ma,
                            const float* __restrict__ va, const float* __restrict__ ba) {
    int t = blockIdx.x * blockDim.x + threadIdx.x;
    int stride = gridDim.x * blockDim.x;
    const int mats[5] = {0, 1, 2, 4, 6};
    for (int idx = t; idx < 5*128*128; idx += stride) {
        int m = idx >> 14, r = idx & 16383, d = r >> 7, k = r & 127;
        int mm = mats[m];
        float rs = rsqrtf(v7[mm*128 + d] + BN_EPS);
        float w = W7[(mm*128 + k)*128 + d] * rs;
        g_WtA[idx] = __uint_as_float(f2tf(__float_as_uint(w)));
        if (k == 0) g_biasA[m*128 + d] = b7[mm*128 + d] - m7[mm*128 + d]*rs;
    }
    for (int idx = t; idx < 128*128; idx += stride) {
        int d = idx >> 7, k = idx & 127;
        float rs3 = rsqrtf(v7[3*128 + d] + BN_EPS);
        float rs5 = rsqrtf(v7[5*128 + d] + BN_EPS);
        g_Wt3[idx] = __uint_as_float(f2tf(__float_as_uint(W7[(3*128 + k)*128 + d] * rs3)));
        g_Wt5[idx] = __uint_as_float(f2tf(__float_as_uint(W7[(5*128 + k)*128 + d] * rs5)));
        if (k == 0) {
            g_b3[d] = b7[3*128 + d] - m7[3*128 + d]*rs3;
            g_b5[d] = b7[5*128 + d] - m7[5*128 + d]*rs5;
        }
    }
    for (int idx = t; idx < 128*256; idx += stride) {
        int d = idx >> 8, kk = idx & 255;
        float rs = rsqrtf(va[d] + BN_EPS);
        g_WtF[idx] = __uint_as_float(f2tf(__float_as_uint(Wa[kk*128 + d] * rs)));
        if (kk == 0) g_ba[d] = ba[d] - ma[d]*rs;
    }
}

// ---------------- NCHW -> NHWC input transpose (into g_ah) ----------------
__global__ void transpose_in(const float* __restrict__ f) {
    __shared__ float tile[32][33];
    int n = blockIdx.z, hw0 = blockIdx.x * 32, c0 = blockIdx.y * 32;
    int tx = threadIdx.x, ty = threadIdx.y;
    const float* src = f + (size_t)n*CDIM*HWD;
#pragma unroll
    for (int i = 0; i < 32; i += 8)
        tile[ty + i][tx] = src[(size_t)(c0 + ty + i)*HWD + hw0 + tx];
    __syncthreads();
    float* dst = g_ah + (size_t)n*HWD*CDIM;
#pragma unroll
    for (int i = 0; i < 32; i += 8)
        dst[(size_t)(hw0 + ty + i)*CDIM + c0 + tx] = tile[tx][ty + i];
}

// ---------------- tf32 tensor-core GEMM: CTA 128x128, warp 32x64, cp.async 2-stage ----------------
// A: NHWC activations [pixel][k] row-major (k contiguous). B: weights [n][k] row-major.
// MODE 0: A = g_ah (f NHWC), B = g_WtA[y], out {th,ph,g,sch,scv}, relu y<3
// MODE 1: A = (y? g_av:g_ah), B = (y? Wt5:Wt3), +shortcut, relu, out (y? g_ph:g_th)
// MODE 2: A = concat(g_th|g_ph) K=256, B = g_WtF, relu, out g_g
template<int MODE>
__global__ __launch_bounds__(256, 2) void gemm_kernel() {
    __shared__ __align__(16) float SA[2][2560];   // [128][20] padded
    __shared__ __align__(16) float SB[2][2560];   // [128][20] padded
    const int tid = threadIdx.x;
    const int wid = tid >> 5, lane = tid & 31;
    const int p0 = blockIdx.x * 128;
    const int y = blockIdx.y;
    const int wm = (wid & 3) * 32;      // warp M offset
    const int wn = (wid >> 2) * 64;     // warp N offset

    const int KT = (MODE == 2) ? 16 : 8;   // 16-wide k tiles
    const float* Abase0; const float* Bp; int ldk;
    if (MODE == 0)      { Abase0 = g_ah;                   Bp = g_WtA + y*16384;        ldk = 128; }
    else if (MODE == 1) { Abase0 = y ? g_av : g_ah;        Bp = y ? g_Wt5 : g_Wt3;      ldk = 128; }
    else                { Abase0 = g_th; /*switches at t=8*/ Bp = g_WtF;                ldk = 256; }

    uint32_t sa_u32 = (uint32_t)__cvta_generic_to_shared(&SA[0][0]);
    uint32_t sb_u32 = (uint32_t)__cvta_generic_to_shared(&SB[0][0]);

    // per-lane ldmatrix base addresses (tile row layout described in theory)
    const int tl = lane >> 3, l7 = lane & 7;
    uint32_t a_base[2], b_base[4];
#pragma unroll
    for (int mt = 0; mt < 2; mt++) {
        int arow = wm + mt*16 + ((tl & 1) << 3) + l7;
        int aword = (tl >> 1) << 2;
        a_base[mt] = sa_u32 + (uint32_t)(arow*20 + aword)*4;
    }
#pragma unroll
    for (int ntp = 0; ntp < 4; ntp++) {
        int brow = wn + ntp*16 + ((tl >> 1) << 3) + l7;
        int bword = (tl & 1) << 2;
        b_base[ntp] = sb_u32 + (uint32_t)(brow*20 + bword)*4;
    }

    float acc[2][8][4];
#pragma unroll
    for (int mt = 0; mt < 2; mt++)
#pragma unroll
        for (int nt = 0; nt < 8; nt++)
#pragma unroll
            for (int q = 0; q < 4; q++) acc[mt][nt][q] = 0.f;

    auto load_tile = [&](int t, int buf) {
        int k0 = t * 16;
        const float* asrc;
        if (MODE == 2) asrc = ((t < 8) ? g_th : g_ph) + (size_t)p0*128 + (k0 & 127);
        else           asrc = Abase0 + (size_t)p0*128 + k0;
        uint32_t sab = sa_u32 + (uint32_t)buf*10240;
        uint32_t sbb = sb_u32 + (uint32_t)buf*10240;
#pragma unroll
        for (int i = 0; i < 2; i++) {
            int id = tid + i*256;            // 512 16B chunks
            int p = id >> 2, q = id & 3;
            cpa16(sab + (uint32_t)(p*20 + q*4)*4, asrc + (size_t)p*128 + q*4);
        }
        const float* bsrc = Bp + k0;
#pragma unroll
        for (int i = 0; i < 2; i++) {
            int id = tid + i*256;
            int n = id >> 2, q = id & 3;
            cpa16(sbb + (uint32_t)(n*20 + q*4)*4, bsrc + (size_t)n*ldk + q*4);
        }
        CP_COMMIT();
    };

    load_tile(0, 0);
    int buf = 0;
    for (int t = 0; t < KT; t++) {
        CP_WAIT0();
        __syncthreads();
        if (t + 1 < KT) load_tile(t + 1, buf ^ 1);

        uint32_t boff = (uint32_t)buf * 10240;
#pragma unroll
        for (int s = 0; s < 2; s++) {
            uint32_t a[2][4], b[4][4];
#pragma unroll
            for (int mt = 0; mt < 2; mt++) {
                ldm4(a[mt], a_base[mt] + boff + s*32);
#pragma unroll
                for (int q = 0; q < 4; q++) a[mt][q] = f2tf(a[mt][q]);
            }
#pragma unroll
            for (int ntp = 0; ntp < 4; ntp++)
                ldm4(b[ntp], b_base[ntp] + boff + s*32);
#pragma unroll
            for (int mt = 0; mt < 2; mt++)
#pragma unroll
                for (int ntp = 0; ntp < 4; ntp++) {
                    mma_tf32(acc[mt][ntp*2 + 0], a[mt], &b[ntp][0]);
                    mma_tf32(acc[mt][ntp*2 + 1], a[mt], &b[ntp][2]);
                }
        }
        __syncthreads();
        buf ^= 1;
    }

    // epilogue
    float* outp; const float* biasp; const float* addp = nullptr; bool relu;
    if (MODE == 0) {
        outp = (y==0) ? g_th : (y==1) ? g_ph : (y==2) ? g_g : (y==3) ? g_sch : g_scv;
        biasp = g_biasA + y*128;
        relu = (y < 3);
    } else if (MODE == 1) {
        outp = y ? g_ph : g_th;
        biasp = y ? g_b5 : g_b3;
        addp  = y ? g_scv : g_sch;
        relu = true;
    } else { outp = g_g; biasp = g_ba; relu = true; }

    const int rbase = p0 + wm + (lane >> 2);
#pragma unroll
    for (int nt = 0; nt < 8; nt++) {
        int cb = wn + nt*8 + (lane & 3)*2;
        float b0 = biasp[cb], b1 = biasp[cb + 1];
#pragma unroll
        for (int mt = 0; mt < 2; mt++) {
#pragma unroll
            for (int half = 0; half < 2; half++) {
                int row = rbase + mt*16 + half*8;
                size_t ro = (size_t)row*128 + cb;
                float v0 = acc[mt][nt][half*2 + 0] + b0;
                float v1 = acc[mt][nt][half*2 + 1] + b1;
                if (MODE == 1) {
                    float2 ad = *(const float2*)(addp + ro);
                    v0 += ad.x; v1 += ad.y;
                }
                if (relu) { v0 = fmaxf(v0, 0.f); v1 = fmaxf(v1, 0.f); }
                *(float2*)(outp + ro) = make_float2(v0, v1);
            }
        }
    }
}

// ---------------- axial attention (flash-style, fp32, K/V smem union, 2 CTAs/SM) ----------------
__global__ __launch_bounds__(256, 2) void attn_kernel() {
    extern __shared__ float sm[];
    float* Qs = sm;                  // 8704
    float* KV = Qs + 128*68;         // 8704 (union: K c-major / V row-major)
    float* Ps = KV + 128*68;         // 4352
    float* red_alpha = Ps + 64*68;   // 64
    float* red_l = red_alpha + 64;   // 64

    const int tid = threadIdx.x;
    const int q0 = blockIdx.x * 64;
    const int row = blockIdx.y;
    const int dir = blockIdx.z;

    size_t base; int stride;
    if (dir == 0) { base = (size_t)row * LROW * CDIM; stride = CDIM; }
    else {
        int n = row / WW, w = row % WW;
        base = (size_t)n*HH*WW*CDIM + (size_t)w*CDIM;
        stride = WW*CDIM;
    }
    const float* thp = g_th + base;
    const float* php = g_ph + base;
    const float* gp  = g_g  + base;
    float* outp = (dir == 0 ? g_ah : g_av) + base;

#pragma unroll
    for (int t = 0; t < 8; t++) {
        int id = tid + t*256;
        int i = id >> 5, cq = (id & 31)*4;
        float4 v = *(const float4*)(thp + (size_t)(q0 + i)*stride + cq);
        Qs[(cq+0)*68 + i] = v.x; Qs[(cq+1)*68 + i] = v.y;
        Qs[(cq+2)*68 + i] = v.z; Qs[(cq+3)*68 + i] = v.w;
    }

    const int wid = tid >> 5, lane = tid & 31;
    const int lr = lane & 7, lc = lane >> 3;
    const int ti = (wid & 1)*8 + lr;
    const int tj = (wid >> 1)*4 + lc;
    const int i0 = ti*4, j0 = tj*4, cc0 = tj*8;
    const int grow = tid >> 2, slane = tid & 3;

    ull o2[4][4];
#pragma unroll
    for (int i = 0; i < 4; i++)
#pragma unroll
        for (int q = 0; q < 4; q++) o2[i][q] = 0ull;
    float m_run = -1e30f, l_run = 0.f;
    const float scale = 0.08838834764831845f;

    for (int kb = 0; kb < LROW; kb += 64) {
        __syncthreads();
#pragma unroll
        for (int t = 0; t < 8; t++) {
            int id = tid + t*256;
            int j = id >> 5, cq = (id & 31)*4;
            float4 v = *(const float4*)(php + (size_t)(kb + j)*stride + cq);
            KV[(cq+0)*68 + j] = v.x; KV[(cq+1)*68 + j] = v.y;
            KV[(cq+2)*68 + j] = v.z; KV[(cq+3)*68 + j] = v.w;
        }
        __syncthreads();

        ull s2[4][2];
#pragma unroll
        for (int i = 0; i < 4; i++) { s2[i][0] = 0ull; s2[i][1] = 0ull; }
#pragma unroll 8
        for (int c = 0; c < CDIM; c++) {
            float4 q4 = *(const float4*)&Qs[c*68 + i0];
            float aq[4] = {q4.x, q4.y, q4.z, q4.w};
            longlong2 kk2 = *(const longlong2*)&KV[c*68 + j0];
            ull k2[2] = {(ull)kk2.x, (ull)kk2.y};
#pragma unroll
            for (int i = 0; i < 4; i++) {
                ull ad = pack2(aq[i], aq[i]);
                s2[i][0] = ffma2(ad, k2[0], s2[i][0]);
                s2[i][1] = ffma2(ad, k2[1], s2[i][1]);
            }
        }
#pragma unroll
        for (int i = 0; i < 4; i++) {
            float2 p0f = unpack2(s2[i][0]);
            float2 p1f = unpack2(s2[i][1]);
            *(float4*)&Ps[(i0 + i)*68 + j0] =
                make_float4(p0f.x*scale, p0f.y*scale, p1f.x*scale, p1f.y*scale);
        }
        __syncthreads();

#pragma unroll
        for (int t = 0; t < 8; t++) {
            int id = tid + t*256;
            int j = id >> 5, cq = (id & 31)*4;
            *(float4*)&KV[j*132 + cq] = *(const float4*)(gp + (size_t)(kb + j)*stride + cq);
        }

        float mx = -1e30f;
#pragma unroll
        for (int jj = 0; jj < 16; jj++)
            mx = fmaxf(mx, Ps[grow*68 + jj*4 + slane]);
        mx = fmaxf(mx, __shfl_xor_sync(0xffffffffu, mx, 1));
        mx = fmaxf(mx, __shfl_xor_sync(0xffffffffu, mx, 2));
        float m_new = fmaxf(m_run, mx);
        float alpha = __expf(m_run - m_new);
        float ssum = 0.f;
#pragma unroll
        for (int jj = 0; jj < 16; jj++) {
            int idx = grow*68 + jj*4 + slane;
            float e = __expf(Ps[idx] - m_new);
            Ps[idx] = e;
            ssum += e;
        }
        ssum += __shfl_xor_sync(0xffffffffu, ssum, 1);
        ssum += __shfl_xor_sync(0xffffffffu, ssum, 2);
        l_run = l_run * alpha + ssum;
        m_run = m_new;
        if (slane == 0) red_alpha[grow] = alpha;
        __syncthreads();

#pragma unroll
        for (int i = 0; i < 4; i++) {
            float al = red_alpha[i0 + i];
            ull ap = pack2(al, al);
#pragma unroll
            for (int q = 0; q < 4; q++) o2[i][q] = fmul2(o2[i][q], ap);
        }
#pragma unroll 4
        for (int j = 0; j < 64; j++) {
            longlong2 v0 = *(const longlong2*)&KV[j*132 + cc0];
            longlong2 v1 = *(const longlong2*)&KV[j*132 + cc0 + 4];
            ull vv[4] = {(ull)v0.x, (ull)v0.y, (ull)v1.x, (ull)v1.y};
            float pp[4];
#pragma unroll
            for (int i = 0; i < 4; i++) pp[i] = Ps[(i0 + i)*68 + j];
#pragma unroll
            for (int i = 0; i < 4; i++) {
                ull pd = pack2(pp[i], pp[i]);
#pragma unroll
                for (int q = 0; q < 4; q++)
                    o2[i][q] = ffma2(pd, vv[q], o2[i][q]);
            }
        }
    }

    if (slane == 0) red_l[grow] = l_run;
    __syncthreads();
#pragma unroll
    for (int i = 0; i < 4; i++) {
        float inv = 1.f / red_l[i0 + i];
        ull ip = pack2(inv, inv);
        float2 r0f = unpack2(fmul2(o2[i][0], ip));
        float2 r1f = unpack2(fmul2(o2[i][1], ip));
        float2 r2f = unpack2(fmul2(o2[i][2], ip));
        float2 r3f = unpack2(fmul2(o2[i][3], ip));
        float* dst = outp + (size_t)(q0 + i0 + i)*stride + cc0;
        *(float4*)dst       = make_float4(r0f.x, r0f.y, r1f.x, r1f.y);
        *(float4*)(dst + 4) = make_float4(r2f.x, r2f.y, r3f.x, r3f.y);
    }
}

// ---------------- NHWC -> NCHW output transpose ----------------
__global__ void transpose_out(float* __restrict__ out) {
    __shared__ float tile[32][33];
    int n = blockIdx.z;
    int hw0 = blockIdx.x * 32;
    int c0 = blockIdx.y * 32;
    int tx = threadIdx.x, ty = threadIdx.y;
    const float* src = g_g + (size_t)n*HWD*CDIM;
#pragma unroll
    for (int i = 0; i < 32; i += 8)
        tile[ty + i][tx] = src[(size_t)(hw0 + ty + i)*CDIM + c0 + tx];
    __syncthreads();
    float* dst = out + (size_t)n*CDIM*HWD;
#pragma unroll
    for (int i = 0; i < 32; i += 8)
        dst[(size_t)(c0 + ty + i)*HWD + hw0 + tx] = tile[tx][ty + i];
}

// ---------------- launch ----------------
extern "C" void kernel_launch(void* const* d_in, const int* in_sizes, int n_in,
                              void* d_out, int out_size) {
    const float* f  = (const float*)d_in[0];
    const float* W7 = (const float*)d_in[1];
    const float* m7 = (const float*)d_in[2];
    const float* v7 = (const float*)d_in[3];
    const float* b7 = (const float*)d_in[4];
    const float* Wa = (const float*)d_in[5];
    const float* ma = (const float*)d_in[6];
    const float* va = (const float*)d_in[7];
    const float* ba = (const float*)d_in[8];
    float* out = (float*)d_out;

    prep_kernel<<<64, 256>>>(W7, m7, v7, b7, Wa, ma, va, ba);

    // f NCHW -> NHWC into g_ah (free until attention overwrites it)
    transpose_in<<<dim3(HWD/32, CDIM/32, NB), dim3(32, 8)>>>(f);

    // stage A: theta, phi, g, sc_h, sc_v (tensor-core tf32)
    gemm_kernel<0><<<dim3(PTOT/128, 5), 256>>>();

    // axial attention (fp32)
    int smem_bytes = (8704 + 8704 + 4352 + 128) * 4;
    cudaFuncSetAttribute(attn_kernel, cudaFuncAttributeMaxDynamicSharedMemorySize, smem_bytes);
    attn_kernel<<<dim3(LROW/64, NROWS, 2), 256, smem_bytes>>>();

    // C1: u/v with shortcut add + relu
    gemm_kernel<1><<<dim3(PTOT/128, 2), 256>>>();

    // C2: final conv over concat(u, v), K=256
    gemm_kernel<2><<<dim3(PTOT/128, 1), 256>>>();

    // NHWC -> NCHW
    transpose_out<<<dim3(HWD/32, CDIM/32, NB), dim3(32, 8)>>>(out);
}

// round 8
// speedup vs baseline: 2.6336x; 1.9185x over previous
#include <cuda_runtime.h>
#include <math.h>
#include <cstdint>

#define NB 8
#define CDIM 128
#define HH 192
#define WW 192
#define HWD (HH*WW)          // 36864
#define PTOT (NB*HWD)        // 294912
#define LROW 192
#define NROWS (NB*HH)        // 1536
#define BN_EPS 1e-5f

typedef unsigned long long ull;

// ---------------- cp.async / ldmatrix / mma helpers (family-portable) ----------------
__device__ __forceinline__ void cpa16(uint32_t s, const float* g) {
    asm volatile("cp.async.ca.shared.global [%0], [%1], 16;" :: "r"(s), "l"(g));
}
#define CP_COMMIT() asm volatile("cp.async.commit_group;" ::: "memory")
#define CP_WAIT0()  asm volatile("cp.async.wait_group 0;" ::: "memory")

__device__ __forceinline__ void ldm4(uint32_t* r, uint32_t addr) {
    asm volatile("ldmatrix.sync.aligned.m8n8.x4.shared.b16 {%0,%1,%2,%3}, [%4];"
                 : "=r"(r[0]), "=r"(r[1]), "=r"(r[2]), "=r"(r[3]) : "r"(addr));
}
__device__ __forceinline__ uint32_t f2tf(uint32_t x) {
    uint32_t y;
    asm("cvt.rna.tf32.f32 %0, %1;" : "=r"(y) : "r"(x));
    return y;
}
__device__ __forceinline__ float tf32r(float x) {
    uint32_t y;
    asm("cvt.rna.tf32.f32 %0, %1;" : "=r"(y) : "f"(x));
    return __uint_as_float(y);
}
__device__ __forceinline__ void mma_tf32(float* d, const uint32_t* a, const uint32_t* b) {
    asm volatile(
        "mma.sync.aligned.m16n8k8.row.col.f32.tf32.tf32.f32 "
        "{%0,%1,%2,%3}, {%4,%5,%6,%7}, {%8,%9}, {%0,%1,%2,%3};"
        : "+f"(d[0]), "+f"(d[1]), "+f"(d[2]), "+f"(d[3])
        : "r"(a[0]), "r"(a[1]), "r"(a[2]), "r"(a[3]), "r"(b[0]), "r"(b[1]));
}

// ---------------- device scratch ----------------
__device__ float g_th [PTOT*CDIM];   // theta, later u = f_h
__device__ float g_ph [PTOT*CDIM];   // phi,   later v = f_v
__device__ float g_g  [PTOT*CDIM];   // g,     later final NHWC tmp
__device__ float g_sch[PTOT*CDIM];
__device__ float g_scv[PTOT*CDIM];
__device__ float g_ah [PTOT*CDIM];   // f_common NHWC before attention; attn-h out after
__device__ float g_av [PTOT*CDIM];

__device__ float g_WtA[5*CDIM*CDIM]; // [mat][d][k] folded, transposed, tf32-rounded
__device__ float g_biasA[5*CDIM];
__device__ float g_Wt3[CDIM*CDIM];
__device__ float g_b3[CDIM];
__device__ float g_Wt5[CDIM*CDIM];
__device__ float g_b5[CDIM];
__device__ float g_WtF[CDIM*2*CDIM];
__device__ float g_ba[CDIM];

// ---------------- BN folding prep ----------------
__global__ void prep_kernel(const float* __restrict__ W7, const float* __restrict__ m7,
                            const float* __restrict__ v7, const float* __restrict__ b7,
                            const float* __restrict__ Wa, const float* __restrict__ ma,
                            const float* __restrict__ va, const float* __restrict__ ba) {
    int t = blockIdx.x * blockDim.x + threadIdx.x;
    int stride = gridDim.x * blockDim.x;
    const int mats[5] = {0, 1, 2, 4, 6};
    for (int idx = t; idx < 5*128*128; idx += stride) {
        int m = idx >> 14, r = idx & 16383, d = r >> 7, k = r & 127;
        int mm = mats[m];
        float rs = rsqrtf(v7[mm*128 + d] + BN_EPS);
        g_WtA[idx] = tf32r(W7[(mm*128 + k)*128 + d] * rs);
        if (k == 0) g_biasA[m*128 + d] = b7[mm*128 + d] - m7[mm*128 + d]*rs;
    }
    for (int idx = t; idx < 128*128; idx += stride) {
        int d = idx >> 7, k = idx & 127;
        float rs3 = rsqrtf(v7[3*128 + d] + BN_EPS);
        float rs5 = rsqrtf(v7[5*128 + d] + BN_EPS);
        g_Wt3[idx] = tf32r(W7[(3*128 + k)*128 + d] * rs3);
        g_Wt5[idx] = tf32r(W7[(5*128 + k)*128 + d] * rs5);
        if (k == 0) {
            g_b3[d] = b7[3*128 + d] - m7[3*128 + d]*rs3;
            g_b5[d] = b7[5*128 + d] - m7[5*128 + d]*rs5;
        }
    }
    for (int idx = t; idx < 128*256; idx += stride) {
        int d = idx >> 8, kk = idx & 255;
        float rs = rsqrtf(va[d] + BN_EPS);
        g_WtF[idx] = tf32r(Wa[kk*128 + d] * rs);
        if (kk == 0) g_ba[d] = ba[d] - ma[d]*rs;
    }
}

// ---------------- NCHW -> NHWC input transpose (into g_ah) ----------------
__global__ void transpose_in(const float* __restrict__ f) {
    __shared__ float tile[32][33];
    int n = blockIdx.z, hw0 = blockIdx.x * 32, c0 = blockIdx.y * 32;
    int tx = threadIdx.x, ty = threadIdx.y;
    const float* src = f + (size_t)n*CDIM*HWD;
#pragma unroll
    for (int i = 0; i < 32; i += 8)
        tile[ty + i][tx] = src[(size_t)(c0 + ty + i)*HWD + hw0 + tx];
    __syncthreads();
    float* dst = g_ah + (size_t)n*HWD*CDIM;
#pragma unroll
    for (int i = 0; i < 32; i += 8)
        dst[(size_t)(hw0 + ty + i)*CDIM + c0 + tx] = tile[tx][ty + i];
}

// ---------------- tf32 tensor-core GEMM (unchanged from R6) ----------------
template<int MODE>
__global__ __launch_bounds__(256, 2) void gemm_kernel() {
    __shared__ __align__(16) float SA[2][2560];   // [128][20] padded
    __shared__ __align__(16) float SB[2][2560];
    const int tid = threadIdx.x;
    const int wid = tid >> 5, lane = tid & 31;
    const int p0 = blockIdx.x * 128;
    const int y = blockIdx.y;
    const int wm = (wid & 3) * 32;
    const int wn = (wid >> 2) * 64;

    const int KT = (MODE == 2) ? 16 : 8;
    const float* Abase0; const float* Bp; int ldk;
    if (MODE == 0)      { Abase0 = g_ah;            Bp = g_WtA + y*16384;   ldk = 128; }
    else if (MODE == 1) { Abase0 = y ? g_av : g_ah; Bp = y ? g_Wt5 : g_Wt3; ldk = 128; }
    else                { Abase0 = g_th;            Bp = g_WtF;             ldk = 256; }

    uint32_t sa_u32 = (uint32_t)__cvta_generic_to_shared(&SA[0][0]);
    uint32_t sb_u32 = (uint32_t)__cvta_generic_to_shared(&SB[0][0]);

    const int tl = lane >> 3, l7 = lane & 7;
    uint32_t a_base[2], b_base[4];
#pragma unroll
    for (int mt = 0; mt < 2; mt++) {
        int arow = wm + mt*16 + ((tl & 1) << 3) + l7;
        int aword = (tl >> 1) << 2;
        a_base[mt] = sa_u32 + (uint32_t)(arow*20 + aword)*4;
    }
#pragma unroll
    for (int ntp = 0; ntp < 4; ntp++) {
        int brow = wn + ntp*16 + ((tl >> 1) << 3) + l7;
        int bword = (tl & 1) << 2;
        b_base[ntp] = sb_u32 + (uint32_t)(brow*20 + bword)*4;
    }

    float acc[2][8][4];
#pragma unroll
    for (int mt = 0; mt < 2; mt++)
#pragma unroll
        for (int nt = 0; nt < 8; nt++)
#pragma unroll
            for (int q = 0; q < 4; q++) acc[mt][nt][q] = 0.f;

    auto load_tile = [&](int t, int buf) {
        int k0 = t * 16;
        const float* asrc;
        if (MODE == 2) asrc = ((t < 8) ? g_th : g_ph) + (size_t)p0*128 + (k0 & 127);
        else           asrc = Abase0 + (size_t)p0*128 + k0;
        uint32_t sab = sa_u32 + (uint32_t)buf*10240;
        uint32_t sbb = sb_u32 + (uint32_t)buf*10240;
#pragma unroll
        for (int i = 0; i < 2; i++) {
            int id = tid + i*256;
            int p = id >> 2, q = id & 3;
            cpa16(sab + (uint32_t)(p*20 + q*4)*4, asrc + (size_t)p*128 + q*4);
        }
        const float* bsrc = Bp + k0;
#pragma unroll
        for (int i = 0; i < 2; i++) {
            int id = tid + i*256;
            int n = id >> 2, q = id & 3;
            cpa16(sbb + (uint32_t)(n*20 + q*4)*4, bsrc + (size_t)n*ldk + q*4);
        }
        CP_COMMIT();
    };

    load_tile(0, 0);
    int buf = 0;
    for (int t = 0; t < KT; t++) {
        CP_WAIT0();
        __syncthreads();
        if (t + 1 < KT) load_tile(t + 1, buf ^ 1);

        uint32_t boff = (uint32_t)buf * 10240;
#pragma unroll
        for (int s = 0; s < 2; s++) {
            uint32_t a[2][4], b[4][4];
#pragma unroll
            for (int mt = 0; mt < 2; mt++) {
                ldm4(a[mt], a_base[mt] + boff + s*32);
#pragma unroll
                for (int q = 0; q < 4; q++) a[mt][q] = f2tf(a[mt][q]);
            }
#pragma unroll
            for (int ntp = 0; ntp < 4; ntp++)
                ldm4(b[ntp], b_base[ntp] + boff + s*32);
#pragma unroll
            for (int mt = 0; mt < 2; mt++)
#pragma unroll
                for (int ntp = 0; ntp < 4; ntp++) {
                    mma_tf32(acc[mt][ntp*2 + 0], a[mt], &b[ntp][0]);
                    mma_tf32(acc[mt][ntp*2 + 1], a[mt], &b[ntp][2]);
                }
        }
        __syncthreads();
        buf ^= 1;
    }

    float* outp; const float* biasp; const float* addp = nullptr; bool relu;
    if (MODE == 0) {
        outp = (y==0) ? g_th : (y==1) ? g_ph : (y==2) ? g_g : (y==3) ? g_sch : g_scv;
        biasp = g_biasA + y*128;
        relu = (y < 3);
    } else if (MODE == 1) {
        outp = y ? g_ph : g_th;
        biasp = y ? g_b5 : g_b3;
        addp  = y ? g_scv : g_sch;
        relu = true;
    } else { outp = g_g; biasp = g_ba; relu = true; }

    const int rbase = p0 + wm + (lane >> 2);
#pragma unroll
    for (int nt = 0; nt < 8; nt++) {
        int cb = wn + nt*8 + (lane & 3)*2;
        float b0 = biasp[cb], b1 = biasp[cb + 1];
#pragma unroll
        for (int mt = 0; mt < 2; mt++) {
#pragma unroll
            for (int half = 0; half < 2; half++) {
                int row = rbase + mt*16 + half*8;
                size_t ro = (size_t)row*128 + cb;
                float v0 = acc[mt][nt][half*2 + 0] + b0;
                float v1 = acc[mt][nt][half*2 + 1] + b1;
                if (MODE == 1) {
                    float2 ad = *(const float2*)(addp + ro);
                    v0 += ad.x; v1 += ad.y;
                }
                if (relu) { v0 = fmaxf(v0, 0.f); v1 = fmaxf(v1, 0.f); }
                *(float2*)(outp + ro) = make_float2(v0, v1);
            }
        }
    }
}

// ---------------- axial attention: flash-style on mma.sync tf32 ----------------
// smem: Qs [64][132] rowmaj | KV union (K [64][132] rowmaj / V [128][68] cmaj) |
//       Ps [64][68] | red_alpha[64] | red_l[64]
// V stride 68 floats = 272B (16B multiple: ldmatrix-legal); V filled with
// float4-over-j writes (conflict-free), gmem reads coalesced per-j.
__global__ __launch_bounds__(256, 2) void attn_kernel() {
    extern __shared__ float sm[];
    float* Qs = sm;                   // 8448 floats
    float* KV = Qs + 8448;            // 8704 floats (max of 64*132, 128*68)
    float* Ps = KV + 8704;            // 4352
    float* red_alpha = Ps + 4352;     // 64
    float* red_l = red_alpha + 64;    // 64

    const int tid = threadIdx.x;
    const int wid = tid >> 5, lane = tid & 31;
    const int q0 = blockIdx.x * 64;
    const int brow_idx = blockIdx.y;
    const int dir = blockIdx.z;

    size_t base; int stride;
    if (dir == 0) { base = (size_t)brow_idx * LROW * CDIM; stride = CDIM; }
    else {
        int n = brow_idx / WW, w = brow_idx % WW;
        base = (size_t)n*HH*WW*CDIM + (size_t)w*CDIM;
        stride = WW*CDIM;
    }
    const float* thp = g_th + base;
    const float* php = g_ph + base;
    const float* gp  = g_g  + base;
    float* outp = (dir == 0 ? g_ah : g_av) + base;

    // Q load: scalar coalesced, tf32-rounded, row-major [i][132]
#pragma unroll
    for (int t = 0; t < 32; t++) {
        int id = tid + t*256;
        int i = id >> 7, c = id & 127;
        Qs[i*132 + c] = tf32r(thp[(size_t)(q0 + i)*stride + c]);
    }

    const int tl = lane >> 3, l7 = lane & 7;
    const int wm  = (wid & 3) * 16;       // M offset (both phases)
    const int wns = (wid >> 2) * 32;      // S-phase N offset
    const int wnp = (wid >> 2) * 64;      // PV-phase N offset

    uint32_t qs_u = (uint32_t)__cvta_generic_to_shared(Qs);
    uint32_t kv_u = (uint32_t)__cvta_generic_to_shared(KV);
    uint32_t ps_u = (uint32_t)__cvta_generic_to_shared(Ps);

    uint32_t sa_base = qs_u + (uint32_t)((wm + ((tl & 1) << 3) + l7)*132 + ((tl >> 1) << 2))*4;
    uint32_t sb_base[2];
#pragma unroll
    for (int ntp = 0; ntp < 2; ntp++)
        sb_base[ntp] = kv_u + (uint32_t)((wns + ntp*16 + ((tl >> 1) << 3) + l7)*132 + ((tl & 1) << 2))*4;
    uint32_t pa_base = ps_u + (uint32_t)((wm + ((tl & 1) << 3) + l7)*68 + ((tl >> 1) << 2))*4;
    uint32_t pb_base[4];
#pragma unroll
    for (int ntp = 0; ntp < 4; ntp++)
        pb_base[ntp] = kv_u + (uint32_t)((wnp + ntp*16 + ((tl >> 1) << 3) + l7)*68 + ((tl & 1) << 2))*4;

    const int grow = tid >> 2, slane = tid & 3;
    const int frow = lane >> 2, fcol2 = (lane & 3)*2;

    float o[8][4];
#pragma unroll
    for (int nt = 0; nt < 8; nt++)
#pragma unroll
        for (int q = 0; q < 4; q++) o[nt][q] = 0.f;
    float m_run = -1e30f, l_run = 0.f;
    const float scale = 0.08838834764831845f;   // 1/sqrt(128)

    for (int kb = 0; kb < LROW; kb += 64) {
        __syncthreads();   // prior chunk's PV reads of KV(V) done
        // K chunk: scalar coalesced -> row-major KV[j][132], tf32
#pragma unroll
        for (int t = 0; t < 32; t++) {
            int id = tid + t*256;
            int j = id >> 7, c = id & 127;
            KV[j*132 + c] = tf32r(php[(size_t)(kb + j)*stride + c]);
        }
        __syncthreads();

        // S = Q K^T (warp tile 16x32, 16 k8 steps)
        float sacc[4][4];
#pragma unroll
        for (int nt = 0; nt < 4; nt++)
#pragma unroll
            for (int q = 0; q < 4; q++) sacc[nt][q] = 0.f;
#pragma unroll
        for (int s = 0; s < 16; s++) {
            uint32_t a[4], b0[4], b1[4];
            ldm4(a, sa_base + s*32);
            ldm4(b0, sb_base[0] + s*32);
            ldm4(b1, sb_base[1] + s*32);
            mma_tf32(sacc[0], a, &b0[0]);
            mma_tf32(sacc[1], a, &b0[2]);
            mma_tf32(sacc[2], a, &b1[0]);
            mma_tf32(sacc[3], a, &b1[2]);
        }
        // store scaled S to Ps
#pragma unroll
        for (int nt = 0; nt < 4; nt++) {
            int cb = wns + nt*8 + fcol2;
            *(float2*)&Ps[(wm + frow)*68 + cb] =
                make_float2(sacc[nt][0]*scale, sacc[nt][1]*scale);
            *(float2*)&Ps[(wm + 8 + frow)*68 + cb] =
                make_float2(sacc[nt][2]*scale, sacc[nt][3]*scale);
        }
        __syncthreads();   // S visible; K ldm reads done -> KV free for V

        // V chunk -> c-major KV[c][68]: float4-over-j writes (conflict-free),
        // per-j gmem reads coalesced across lanes (consecutive c)
#pragma unroll
        for (int t = 0; t < 8; t++) {
            int id = tid + t*256;
            int c = id & 127, j0 = (id >> 7) * 4;
            float4 v;
            v.x = tf32r(gp[(size_t)(kb + j0 + 0)*stride + c]);
            v.y = tf32r(gp[(size_t)(kb + j0 + 1)*stride + c]);
            v.z = tf32r(gp[(size_t)(kb + j0 + 2)*stride + c]);
            v.w = tf32r(gp[(size_t)(kb + j0 + 3)*stride + c]);
            *(float4*)&KV[c*68 + j0] = v;
        }

        // online softmax (4 threads/row), exp written back tf32-rounded
        float mx = -1e30f;
#pragma unroll
        for (int jj = 0; jj < 16; jj++)
            mx = fmaxf(mx, Ps[grow*68 + jj*4 + slane]);
        mx = fmaxf(mx, __shfl_xor_sync(0xffffffffu, mx, 1));
        mx = fmaxf(mx, __shfl_xor_sync(0xffffffffu, mx, 2));
        float m_new = fmaxf(m_run, mx);
        float alpha = __expf(m_run - m_new);
        float ssum = 0.f;
#pragma unroll
        for (int jj = 0; jj < 16; jj++) {
            int idx = grow*68 + jj*4 + slane;
            float e = tf32r(__expf(Ps[idx] - m_new));
            Ps[idx] = e;
            ssum += e;
        }
        ssum += __shfl_xor_sync(0xffffffffu, ssum, 1);
        ssum += __shfl_xor_sync(0xffffffffu, ssum, 2);
        l_run = l_run * alpha + ssum;
        m_run = m_new;
        if (slane == 0) red_alpha[grow] = alpha;
        __syncthreads();   // V, exp(S), alpha visible

        // O = O*alpha + P V (warp tile 16x64, 8 k8 steps)
        {
            float al0 = red_alpha[wm + frow];
            float al1 = red_alpha[wm + 8 + frow];
#pragma unroll
            for (int nt = 0; nt < 8; nt++) {
                o[nt][0] *= al0; o[nt][1] *= al0;
                o[nt][2] *= al1; o[nt][3] *= al1;
            }
        }
#pragma unroll
        for (int s = 0; s < 8; s++) {
            uint32_t a[4];
            ldm4(a, pa_base + s*32);
#pragma unroll
            for (int ntp = 0; ntp < 4; ntp++) {
                uint32_t b[4];
                ldm4(b, pb_base[ntp] + s*32);
                mma_tf32(o[ntp*2 + 0], a, &b[0]);
                mma_tf32(o[ntp*2 + 1], a, &b[2]);
            }
        }
    }

    if (slane == 0) red_l[grow] = l_run;
    __syncthreads();
    {
        float inv0 = 1.f / red_l[wm + frow];
        float inv1 = 1.f / red_l[wm + 8 + frow];
        int r0 = q0 + wm + frow;
#pragma unroll
        for (int nt = 0; nt < 8; nt++) {
            int cb = wnp + nt*8 + fcol2;
            *(float2*)&outp[(size_t)r0*stride + cb] =
                make_float2(o[nt][0]*inv0, o[nt][1]*inv0);
            *(float2*)&outp[(size_t)(r0 + 8)*stride + cb] =
                make_float2(o[nt][2]*inv1, o[nt][3]*inv1);
        }
    }
}

// ---------------- NHWC -> NCHW output transpose ----------------
__global__ void transpose_out(float* __restrict__ out) {
    __shared__ float tile[32][33];
    int n = blockIdx.z;
    int hw0 = blockIdx.x * 32;
    int c0 = blockIdx.y * 32;
    int tx = threadIdx.x, ty = threadIdx.y;
    const float* src = g_g + (size_t)n*HWD*CDIM;
#pragma unroll
    for (int i = 0; i < 32; i += 8)
        tile[ty + i][tx] = src[(size_t)(hw0 + ty + i)*CDIM + c0 + tx];
    __syncthreads();
    float* dst = out + (size_t)n*CDIM*HWD;
#pragma unroll
    for (int i = 0; i < 32; i += 8)
        dst[(size_t)(c0 + ty + i)*HWD + hw0 + tx] = tile[tx][ty + i];
}

// ---------------- launch ----------------
extern "C" void kernel_launch(void* const* d_in, const int* in_sizes, int n_in,
                              void* d_out, int out_size) {
    const float* f  = (const float*)d_in[0];
    const float* W7 = (const float*)d_in[1];
    const float* m7 = (const float*)d_in[2];
    const float* v7 = (const float*)d_in[3];
    const float* b7 = (const float*)d_in[4];
    const float* Wa = (const float*)d_in[5];
    const float* ma = (const float*)d_in[6];
    const float* va = (const float*)d_in[7];
    const float* ba = (const float*)d_in[8];
    float* out = (float*)d_out;

    prep_kernel<<<64, 256>>>(W7, m7, v7, b7, Wa, ma, va, ba);

    transpose_in<<<dim3(HWD/32, CDIM/32, NB), dim3(32, 8)>>>(f);

    gemm_kernel<0><<<dim3(PTOT/128, 5), 256>>>();

    int smem_bytes = (8448 + 8704 + 4352 + 128) * 4;   // 86528
    cudaFuncSetAttribute(attn_kernel, cudaFuncAttributeMaxDynamicSharedMemorySize, smem_bytes);
    attn_kernel<<<dim3(LROW/64, NROWS, 2), 256, smem_bytes>>>();

    gemm_kernel<1><<<dim3(PTOT/128, 2), 256>>>();
    gemm_kernel<2><<<dim3(PTOT/128, 1), 256>>>();

    transpose_out<<<dim3(HWD/32, CDIM/32, NB), dim3(32, 8)>>>(out);
}

// round 9
// speedup vs baseline: 2.9226x; 1.1097x over previous
#include <cuda_runtime.h>
#include <math.h>
#include <cstdint>

#define NB 8
#define CDIM 128
#define HH 192
#define WW 192
#define HWD (HH*WW)          // 36864
#define PTOT (NB*HWD)        // 294912
#define LROW 192
#define NROWS (NB*HH)        // 1536
#define BN_EPS 1e-5f

// ---------------- cp.async / ldmatrix / mma helpers (family-portable) ----------------
__device__ __forceinline__ void cpa16(uint32_t s, const float* g) {
    asm volatile("cp.async.ca.shared.global [%0], [%1], 16;" :: "r"(s), "l"(g));
}
#define CP_COMMIT() asm volatile("cp.async.commit_group;" ::: "memory")
#define CP_WAIT0()  asm volatile("cp.async.wait_group 0;" ::: "memory")

__device__ __forceinline__ void ldm4(uint32_t* r, uint32_t addr) {
    asm volatile("ldmatrix.sync.aligned.m8n8.x4.shared.b16 {%0,%1,%2,%3}, [%4];"
                 : "=r"(r[0]), "=r"(r[1]), "=r"(r[2]), "=r"(r[3]) : "r"(addr));
}
__device__ __forceinline__ uint32_t f2tf(uint32_t x) {
    uint32_t y;
    asm("cvt.rna.tf32.f32 %0, %1;" : "=r"(y) : "r"(x));
    return y;
}
__device__ __forceinline__ float tf32r(float x) {
    uint32_t y;
    asm("cvt.rna.tf32.f32 %0, %1;" : "=r"(y) : "f"(x));
    return __uint_as_float(y);
}
__device__ __forceinline__ void mma_tf32(float* d, const uint32_t* a, const uint32_t* b) {
    asm volatile(
        "mma.sync.aligned.m16n8k8.row.col.f32.tf32.tf32.f32 "
        "{%0,%1,%2,%3}, {%4,%5,%6,%7}, {%8,%9}, {%0,%1,%2,%3};"
        : "+f"(d[0]), "+f"(d[1]), "+f"(d[2]), "+f"(d[3])
        : "r"(a[0]), "r"(a[1]), "r"(a[2]), "r"(a[3]), "r"(b[0]), "r"(b[1]));
}

// ---------------- device scratch ----------------
__device__ float g_th [PTOT*CDIM];   // theta (tf32-rounded), later u = f_h
__device__ float g_ph [PTOT*CDIM];   // phi   (tf32-rounded), later v = f_v
__device__ float g_g  [PTOT*CDIM];   // g     (tf32-rounded)
__device__ float g_sch[PTOT*CDIM];
__device__ float g_scv[PTOT*CDIM];
__device__ float g_ah [PTOT*CDIM];   // f_common NHWC before attention; attn-h out after
__device__ float g_av [PTOT*CDIM];

__device__ float g_WtA[5*CDIM*CDIM]; // [mat][d][k] folded, transposed, tf32-rounded
__device__ float g_biasA[5*CDIM];
__device__ float g_Wt3[CDIM*CDIM];
__device__ float g_b3[CDIM];
__device__ float g_Wt5[CDIM*CDIM];
__device__ float g_b5[CDIM];
__device__ float g_WtF[CDIM*2*CDIM];
__device__ float g_ba[CDIM];

// ---------------- BN folding prep ----------------
__global__ void prep_kernel(const float* __restrict__ W7, const float* __restrict__ m7,
                            const float* __restrict__ v7, const float* __restrict__ b7,
                            const float* __restrict__ Wa, const float* __restrict__ ma,
                            const float* __restrict__ va, const float* __restrict__ ba) {
    int t = blockIdx.x * blockDim.x + threadIdx.x;
    int stride = gridDim.x * blockDim.x;
    const int mats[5] = {0, 1, 2, 4, 6};
    for (int idx = t; idx < 5*128*128; idx += stride) {
        int m = idx >> 14, r = idx & 16383, d = r >> 7, k = r & 127;
        int mm = mats[m];
        float rs = rsqrtf(v7[mm*128 + d] + BN_EPS);
        g_WtA[idx] = tf32r(W7[(mm*128 + k)*128 + d] * rs);
        if (k == 0) g_biasA[m*128 + d] = b7[mm*128 + d] - m7[mm*128 + d]*rs;
    }
    for (int idx = t; idx < 128*128; idx += stride) {
        int d = idx >> 7, k = idx & 127;
        float rs3 = rsqrtf(v7[3*128 + d] + BN_EPS);
        float rs5 = rsqrtf(v7[5*128 + d] + BN_EPS);
        g_Wt3[idx] = tf32r(W7[(3*128 + k)*128 + d] * rs3);
        g_Wt5[idx] = tf32r(W7[(5*128 + k)*128 + d] * rs5);
        if (k == 0) {
            g_b3[d] = b7[3*128 + d] - m7[3*128 + d]*rs3;
            g_b5[d] = b7[5*128 + d] - m7[5*128 + d]*rs5;
        }
    }
    for (int idx = t; idx < 128*256; idx += stride) {
        int d = idx >> 8, kk = idx & 255;
        float rs = rsqrtf(va[d] + BN_EPS);
        g_WtF[idx] = tf32r(Wa[kk*128 + d] * rs);
        if (kk == 0) g_ba[d] = ba[d] - ma[d]*rs;
    }
}

// ---------------- NCHW -> NHWC input transpose (into g_ah) ----------------
__global__ void transpose_in(const float* __restrict__ f) {
    __shared__ float tile[32][33];
    int n = blockIdx.z, hw0 = blockIdx.x * 32, c0 = blockIdx.y * 32;
    int tx = threadIdx.x, ty = threadIdx.y;
    const float* src = f + (size_t)n*CDIM*HWD;
#pragma unroll
    for (int i = 0; i < 32; i += 8)
        tile[ty + i][tx] = src[(size_t)(c0 + ty + i)*HWD + hw0 + tx];
    __syncthreads();
    float* dst = g_ah + (size_t)n*HWD*CDIM;
#pragma unroll
    for (int i = 0; i < 32; i += 8)
        dst[(size_t)(hw0 + ty + i)*CDIM + c0 + tx] = tile[tx][ty + i];
}

// ---------------- tf32 tensor-core GEMM ----------------
// MODE 0: grid (5, pixblocks): y = mat. A = g_ah, B = g_WtA[y].
//         Outputs th/ph/g tf32-rounded (feed attention); sch/scv raw.
// MODE 1: grid (pixblocks, 2). A = (y? g_av:g_ah), +shortcut, relu.
// MODE 2: grid (pixblocks, 1). K=256; direct NCHW output via smem transpose.
template<int MODE>
__global__ __launch_bounds__(256, 2) void gemm_kernel(float* __restrict__ out) {
    __shared__ __align__(16) float SA[2][2560];   // [128][20] padded
    __shared__ __align__(16) float SB[2][2560];
    const int tid = threadIdx.x;
    const int wid = tid >> 5, lane = tid & 31;
    int p0, y;
    if (MODE == 0) { y = blockIdx.x; p0 = blockIdx.y * 128; }
    else           { y = blockIdx.y; p0 = blockIdx.x * 128; }
    const int wm = (wid & 3) * 32;
    const int wn = (wid >> 2) * 64;

    const int KT = (MODE == 2) ? 16 : 8;
    const float* Abase0; const float* Bp; int ldk;
    if (MODE == 0)      { Abase0 = g_ah;            Bp = g_WtA + y*16384;   ldk = 128; }
    else if (MODE == 1) { Abase0 = y ? g_av : g_ah; Bp = y ? g_Wt5 : g_Wt3; ldk = 128; }
    else                { Abase0 = g_th;            Bp = g_WtF;             ldk = 256; }

    uint32_t sa_u32 = (uint32_t)__cvta_generic_to_shared(&SA[0][0]);
    uint32_t sb_u32 = (uint32_t)__cvta_generic_to_shared(&SB[0][0]);

    const int tl = lane >> 3, l7 = lane & 7;
    uint32_t a_base[2], b_base[4];
#pragma unroll
    for (int mt = 0; mt < 2; mt++) {
        int arow = wm + mt*16 + ((tl & 1) << 3) + l7;
        int aword = (tl >> 1) << 2;
        a_base[mt] = sa_u32 + (uint32_t)(arow*20 + aword)*4;
    }
#pragma unroll
    for (int ntp = 0; ntp < 4; ntp++) {
        int brow = wn + ntp*16 + ((tl >> 1) << 3) + l7;
        int bword = (tl & 1) << 2;
        b_base[ntp] = sb_u32 + (uint32_t)(brow*20 + bword)*4;
    }

    float acc[2][8][4];
#pragma unroll
    for (int mt = 0; mt < 2; mt++)
#pragma unroll
        for (int nt = 0; nt < 8; nt++)
#pragma unroll
            for (int q = 0; q < 4; q++) acc[mt][nt][q] = 0.f;

    auto load_tile = [&](int t, int buf) {
        int k0 = t * 16;
        const float* asrc;
        if (MODE == 2) asrc = ((t < 8) ? g_th : g_ph) + (size_t)p0*128 + (k0 & 127);
        else           asrc = Abase0 + (size_t)p0*128 + k0;
        uint32_t sab = sa_u32 + (uint32_t)buf*10240;
        uint32_t sbb = sb_u32 + (uint32_t)buf*10240;
#pragma unroll
        for (int i = 0; i < 2; i++) {
            int id = tid + i*256;
            int p = id >> 2, q = id & 3;
            cpa16(sab + (uint32_t)(p*20 + q*4)*4, asrc + (size_t)p*128 + q*4);
        }
        const float* bsrc = Bp + k0;
#pragma unroll
        for (int i = 0; i < 2; i++) {
            int id = tid + i*256;
            int n = id >> 2, q = id & 3;
            cpa16(sbb + (uint32_t)(n*20 + q*4)*4, bsrc + (size_t)n*ldk + q*4);
        }
        CP_COMMIT();
    };

    load_tile(0, 0);
    int buf = 0;
    for (int t = 0; t < KT; t++) {
        CP_WAIT0();
        __syncthreads();
        if (t + 1 < KT) load_tile(t + 1, buf ^ 1);

        uint32_t boff = (uint32_t)buf * 10240;
#pragma unroll
        for (int s = 0; s < 2; s++) {
            uint32_t a[2][4], b[4][4];
#pragma unroll
            for (int mt = 0; mt < 2; mt++) {
                ldm4(a[mt], a_base[mt] + boff + s*32);
#pragma unroll
                for (int q = 0; q < 4; q++) a[mt][q] = f2tf(a[mt][q]);
            }
#pragma unroll
            for (int ntp = 0; ntp < 4; ntp++)
                ldm4(b[ntp], b_base[ntp] + boff + s*32);
#pragma unroll
            for (int mt = 0; mt < 2; mt++)
#pragma unroll
                for (int ntp = 0; ntp < 4; ntp++) {
                    mma_tf32(acc[mt][ntp*2 + 0], a[mt], &b[ntp][0]);
                    mma_tf32(acc[mt][ntp*2 + 1], a[mt], &b[ntp][2]);
                }
        }
        __syncthreads();
        buf ^= 1;
    }

    if (MODE == 2) {
        // direct NCHW output: stage [64 c][128 pix] in smem (reuse SA/SB), write coalesced
        const float* biasp = g_ba;
        float* SP = &SA[0][0];                 // 64*129 = 8256 floats <= 10240
        const int n_img = p0 / HWD, hw0 = p0 % HWD;
        float* obase = out + (size_t)n_img*CDIM*HWD + hw0;
#pragma unroll
        for (int ch = 0; ch < 2; ch++) {
            if ((wid >> 2) == ch) {
#pragma unroll
                for (int nt = 0; nt < 8; nt++) {
                    int cb = nt*8 + (lane & 3)*2;            // local col 0..63
                    float b0 = biasp[ch*64 + cb], b1 = biasp[ch*64 + cb + 1];
#pragma unroll
                    for (int mt = 0; mt < 2; mt++)
#pragma unroll
                        for (int half = 0; half < 2; half++) {
                            int row = wm + (lane >> 2) + mt*16 + half*8;
                            SP[cb*129 + row]     = fmaxf(acc[mt][nt][half*2 + 0] + b0, 0.f);
                            SP[(cb+1)*129 + row] = fmaxf(acc[mt][nt][half*2 + 1] + b1, 0.f);
                        }
                }
            }
            __syncthreads();
#pragma unroll
            for (int t2 = 0; t2 < 32; t2++) {
                int id = tid + t2*256;                        // 8192
                int c = id >> 7, pix = id & 127;
                obase[(size_t)(ch*64 + c)*HWD + pix] = SP[c*129 + pix];
            }
            __syncthreads();
        }
        return;
    }

    float* outp; const float* biasp; const float* addp = nullptr; bool relu, rnd;
    if (MODE == 0) {
        outp = (y==0) ? g_th : (y==1) ? g_ph : (y==2) ? g_g : (y==3) ? g_sch : g_scv;
        biasp = g_biasA + y*128;
        relu = (y < 3);
        rnd  = (y < 3);    // th/ph/g feed attention as tf32 operands
    } else {
        outp = y ? g_ph : g_th;
        biasp = y ? g_b5 : g_b3;
        addp  = y ? g_scv : g_sch;
        relu = true; rnd = false;
    }

    const int rbase = p0 + wm + (lane >> 2);
#pragma unroll
    for (int nt = 0; nt < 8; nt++) {
        int cb = wn + nt*8 + (lane & 3)*2;
        float b0 = biasp[cb], b1 = biasp[cb + 1];
#pragma unroll
        for (int mt = 0; mt < 2; mt++) {
#pragma unroll
            for (int half = 0; half < 2; half++) {
                int row = rbase + mt*16 + half*8;
                size_t ro = (size_t)row*128 + cb;
                float v0 = acc[mt][nt][half*2 + 0] + b0;
                float v1 = acc[mt][nt][half*2 + 1] + b1;
                if (MODE == 1) {
                    float2 ad = *(const float2*)(addp + ro);
                    v0 += ad.x; v1 += ad.y;
                }
                if (relu) { v0 = fmaxf(v0, 0.f); v1 = fmaxf(v1, 0.f); }
                if (rnd)  { v0 = tf32r(v0); v1 = tf32r(v1); }
                *(float2*)(outp + ro) = make_float2(v0, v1);
            }
        }
    }
}

// ---------------- axial attention: flash-style on mma.sync tf32 ----------------
// Operands pre-rounded to tf32 at stage-A write -> fills are pure copies.
// smem: Qs [64][132] | KV union (K [64][132] rowmaj / V [128][68] cmaj) |
//       Ps [64][68] | red_alpha[64] | red_l[64]
__global__ __launch_bounds__(256, 2) void attn_kernel() {
    extern __shared__ float sm[];
    float* Qs = sm;                   // 8448 floats
    float* KV = Qs + 8448;            // 8704 floats
    float* Ps = KV + 8704;            // 4352
    float* red_alpha = Ps + 4352;     // 64
    float* red_l = red_alpha + 64;    // 64

    const int tid = threadIdx.x;
    const int wid = tid >> 5, lane = tid & 31;
    const int q0 = blockIdx.x * 64;
    const int brow_idx = blockIdx.y;
    const int dir = blockIdx.z;

    size_t base; int stride;
    if (dir == 0) { base = (size_t)brow_idx * LROW * CDIM; stride = CDIM; }
    else {
        int n = brow_idx / WW, w = brow_idx % WW;
        base = (size_t)n*HH*WW*CDIM + (size_t)w*CDIM;
        stride = WW*CDIM;
    }
    const float* thp = g_th + base;
    const float* php = g_ph + base;
    const float* gp  = g_g  + base;
    float* outp = (dir == 0 ? g_ah : g_av) + base;

    uint32_t qs_u = (uint32_t)__cvta_generic_to_shared(Qs);
    uint32_t kv_u = (uint32_t)__cvta_generic_to_shared(KV);
    uint32_t ps_u = (uint32_t)__cvta_generic_to_shared(Ps);

    // Q load via cp.async (already tf32-rounded in gmem)
#pragma unroll
    for (int t = 0; t < 8; t++) {
        int id = tid + t*256;                   // 2048 16B chunks
        int i = id >> 5, q = id & 31;
        cpa16(qs_u + (uint32_t)(i*132 + q*4)*4, thp + (size_t)(q0 + i)*stride + q*4);
    }
    CP_COMMIT();

    const int tl = lane >> 3, l7 = lane & 7;
    const int wm  = (wid & 3) * 16;
    const int wns = (wid >> 2) * 32;
    const int wnp = (wid >> 2) * 64;

    uint32_t sa_base = qs_u + (uint32_t)((wm + ((tl & 1) << 3) + l7)*132 + ((tl >> 1) << 2))*4;
    uint32_t sb_base[2];
#pragma unroll
    for (int ntp = 0; ntp < 2; ntp++)
        sb_base[ntp] = kv_u + (uint32_t)((wns + ntp*16 + ((tl >> 1) << 3) + l7)*132 + ((tl & 1) << 2))*4;
    uint32_t pa_base = ps_u + (uint32_t)((wm + ((tl & 1) << 3) + l7)*68 + ((tl >> 1) << 2))*4;
    uint32_t pb_base[4];
#pragma unroll
    for (int ntp = 0; ntp < 4; ntp++)
        pb_base[ntp] = kv_u + (uint32_t)((wnp + ntp*16 + ((tl >> 1) << 3) + l7)*68 + ((tl & 1) << 2))*4;

    const int grow = tid >> 2, slane = tid & 3;
    const int frow = lane >> 2, fcol2 = (lane & 3)*2;

    float o[8][4];
#pragma unroll
    for (int nt = 0; nt < 8; nt++)
#pragma unroll
        for (int q = 0; q < 4; q++) o[nt][q] = 0.f;
    float m_run = -1e30f, l_run = 0.f;
    const float scale = 0.08838834764831845f;   // 1/sqrt(128)

    for (int kb = 0; kb < LROW; kb += 64) {
        __syncthreads();   // prior chunk's PV reads of KV(V) done
        // K chunk via cp.async -> row-major KV[j][132]
#pragma unroll
        for (int t = 0; t < 8; t++) {
            int id = tid + t*256;
            int j = id >> 5, q = id & 31;
            cpa16(kv_u + (uint32_t)(j*132 + q*4)*4, php + (size_t)(kb + j)*stride + q*4);
        }
        CP_COMMIT();
        CP_WAIT0();        // also covers Q on first chunk
        __syncthreads();

        // S = Q K^T (warp tile 16x32, 16 k8 steps)
        float sacc[4][4];
#pragma unroll
        for (int nt = 0; nt < 4; nt++)
#pragma unroll
            for (int q = 0; q < 4; q++) sacc[nt][q] = 0.f;
#pragma unroll
        for (int s = 0; s < 16; s++) {
            uint32_t a[4], b0[4], b1[4];
            ldm4(a, sa_base + s*32);
            ldm4(b0, sb_base[0] + s*32);
            ldm4(b1, sb_base[1] + s*32);
            mma_tf32(sacc[0], a, &b0[0]);
            mma_tf32(sacc[1], a, &b0[2]);
            mma_tf32(sacc[2], a, &b1[0]);
            mma_tf32(sacc[3], a, &b1[2]);
        }
#pragma unroll
        for (int nt = 0; nt < 4; nt++) {
            int cb = wns + nt*8 + fcol2;
            *(float2*)&Ps[(wm + frow)*68 + cb] =
                make_float2(sacc[nt][0]*scale, sacc[nt][1]*scale);
            *(float2*)&Ps[(wm + 8 + frow)*68 + cb] =
                make_float2(sacc[nt][2]*scale, sacc[nt][3]*scale);
        }
        __syncthreads();   // S visible; K reads done -> KV free for V

        // V chunk -> c-major KV[c][68] via float4-over-j writes (no cvt needed)
#pragma unroll
        for (int t = 0; t < 8; t++) {
            int id = tid + t*256;
            int c = id & 127, j0 = (id >> 7) * 4;
            float4 v;
            v.x = gp[(size_t)(kb + j0 + 0)*stride + c];
            v.y = gp[(size_t)(kb + j0 + 1)*stride + c];
            v.z = gp[(size_t)(kb + j0 + 2)*stride + c];
            v.w = gp[(size_t)(kb + j0 + 3)*stride + c];
            *(float4*)&KV[c*68 + j0] = v;
        }

        // online softmax (4 threads/row), exp written back tf32-rounded
        float mx = -1e30f;
#pragma unroll
        for (int jj = 0; jj < 16; jj++)
            mx = fmaxf(mx, Ps[grow*68 + jj*4 + slane]);
        mx = fmaxf(mx, __shfl_xor_sync(0xffffffffu, mx, 1));
        mx = fmaxf(mx, __shfl_xor_sync(0xffffffffu, mx, 2));
        float m_new = fmaxf(m_run, mx);
        float alpha = __expf(m_run - m_new);
        float ssum = 0.f;
#pragma unroll
        for (int jj = 0; jj < 16; jj++) {
            int idx = grow*68 + jj*4 + slane;
            float e = tf32r(__expf(Ps[idx] - m_new));
            Ps[idx] = e;
            ssum += e;
        }
        ssum += __shfl_xor_sync(0xffffffffu, ssum, 1);
        ssum += __shfl_xor_sync(0xffffffffu, ssum, 2);
        l_run = l_run * alpha + ssum;
        m_run = m_new;
        if (slane == 0) red_alpha[grow] = alpha;
        __syncthreads();   // V, exp(S), alpha visible

        // O = O*alpha + P V (warp tile 16x64, 8 k8 steps)
        {
            float al0 = red_alpha[wm + frow];
            float al1 = red_alpha[wm + 8 + frow];
#pragma unroll
            for (int nt = 0; nt < 8; nt++) {
                o[nt][0] *= al0; o[nt][1] *= al0;
                o[nt][2] *= al1; o[nt][3] *= al1;
            }
        }
#pragma unroll
        for (int s = 0; s < 8; s++) {
            uint32_t a[4];
            ldm4(a, pa_base + s*32);
#pragma unroll
            for (int ntp = 0; ntp < 4; ntp++) {
                uint32_t b[4];
                ldm4(b, pb_base[ntp] + s*32);
                mma_tf32(o[ntp*2 + 0], a, &b[0]);
                mma_tf32(o[ntp*2 + 1], a, &b[2]);
            }
        }
    }

    if (slane == 0) red_l[grow] = l_run;
    __syncthreads();
    {
        float inv0 = 1.f / red_l[wm + frow];
        float inv1 = 1.f / red_l[wm + 8 + frow];
        int r0 = q0 + wm + frow;
#pragma unroll
        for (int nt = 0; nt < 8; nt++) {
            int cb = wnp + nt*8 + fcol2;
            *(float2*)&outp[(size_t)r0*stride + cb] =
                make_float2(o[nt][0]*inv0, o[nt][1]*inv0);
            *(float2*)&outp[(size_t)(r0 + 8)*stride + cb] =
                make_float2(o[nt][2]*inv1, o[nt][3]*inv1);
        }
    }
}

// ---------------- launch ----------------
extern "C" void kernel_launch(void* const* d_in, const int* in_sizes, int n_in,
                              void* d_out, int out_size) {
    const float* f  = (const float*)d_in[0];
    const float* W7 = (const float*)d_in[1];
    const float* m7 = (const float*)d_in[2];
    const float* v7 = (const float*)d_in[3];
    const float* b7 = (const float*)d_in[4];
    const float* Wa = (const float*)d_in[5];
    const float* ma = (const float*)d_in[6];
    const float* va = (const float*)d_in[7];
    const float* ba = (const float*)d_in[8];
    float* out = (float*)d_out;

    prep_kernel<<<64, 256>>>(W7, m7, v7, b7, Wa, ma, va, ba);

    transpose_in<<<dim3(HWD/32, CDIM/32, NB), dim3(32, 8)>>>(f);

    // stage A: grid (5 mats, pixel blocks) so A tiles are L2-reused across mats
    gemm_kernel<0><<<dim3(5, PTOT/128), 256>>>(nullptr);

    int smem_bytes = (8448 + 8704 + 4352 + 128) * 4;   // 86528
    cudaFuncSetAttribute(attn_kernel, cudaFuncAttributeMaxDynamicSharedMemorySize, smem_bytes);
    attn_kernel<<<dim3(LROW/64, NROWS, 2), 256, smem_bytes>>>();

    gemm_kernel<1><<<dim3(PTOT/128, 2), 256>>>(nullptr);

    // final conv writes NCHW output directly
    gemm_kernel<2><<<dim3(PTOT/128, 1), 256>>>(out);
}